// round 3
// baseline (speedup 1.0000x reference)
#include <cuda_runtime.h>

// SorscherRNN forward:
//   h0 = p0 @ W_init^T                                 [64, 4096]
//   loop t = 0..99 (sequential):
//     z  = v_t @ W_ih^T + h @ W_hh^T - 0.1 * va
//     va = va + 0.9 * (z_prev - va)
//     s  = relu(z);  h <- s;  z_prev <- z;  g[:,t,:] = s
//   out = g @ W_dec^T                                   [64, 100, 512]
//
// Shapes: B=64, T=100, NG=4096, NP=512. All fp32.

#define NG 4096
#define NP 512
#define BB 64
#define TT 100

// Scratch state (allocation-free: __device__ globals)
__device__ float d_g[BB * TT * NG];   // relu outputs s for every step (≈105 MB)
__device__ float d_h0[BB * NG];       // initial hidden state
__device__ float d_va[BB * NG];       // adaptation state
__device__ float d_zp[BB * NG];       // previous (post-subtraction) z

// Reset recurrent state every call (graph replays must be deterministic).
__global__ void zero_state_kernel() {
  int i = blockIdx.x * blockDim.x + threadIdx.x;
  int stride = gridDim.x * blockDim.x;
  for (int k = i; k < BB * NG; k += stride) {
    d_va[k] = 0.0f;
    d_zp[k] = 0.0f;
  }
}

// Tiled GEMM: OUT[64 x 32-tile] = A[64 x K] @ W[Ntile x K]^T
//   MODE 0: h0 = p0 @ W_init^T              (A=p0, lda=NP, K=NP, out=d_h0)
//   MODE 1: one recurrence step t           (A from d_h0 / d_g, K=NG, fused epilogue)
//   MODE 2: decode out = g @ W_dec^T        (A=d_g rows via blockIdx.y, K=NG, out=param)
//
// Block: 256 threads; tile 64(m) x 32(n); thread tile 4m x 2n.
// K-chunks of 32, register-prefetch double buffering of global loads.
template <int MODE>
__global__ void gemm_kernel(const float* __restrict__ Ap,
                            const float* __restrict__ W,
                            const float* __restrict__ v,
                            const float* __restrict__ Wih,
                            float* __restrict__ outp,
                            int K, int t) {
  // hs: transposed h chunk [k][m], padded so rows are 16B-aligned (68*4=272B)
  // ws: transposed W chunk [k][n], padded so rows are 8B-aligned (34*4=136B)
  __shared__ __align__(16) float hs[32][68];
  __shared__ __align__(16) float ws[32][34];

  const int tid = threadIdx.x;
  const int tx = tid & 15;   // n position: n = nb + tx*2 + {0,1}
  const int ty = tid >> 4;   // m position: m = ty*4 + {0..3}
  const int lk = tid & 31;   // loader: k within chunk
  const int lr = tid >> 5;   // loader: row group 0..7
  const int nb = blockIdx.x * 32;

  const float* A;
  int lda;
  if (MODE == 0) {
    A = Ap; lda = NP;
  } else if (MODE == 1) {
    if (t == 0) { A = d_h0;               lda = NG;      }
    else        { A = d_g + (t - 1) * NG; lda = TT * NG; }  // row m = g[m][t-1][:]
  } else {
    A = d_g + (size_t)blockIdx.y * 64 * NG; lda = NG;       // g viewed as [6400 x NG]
  }

  float acc[4][2];
#pragma unroll
  for (int i = 0; i < 4; i++) { acc[i][0] = 0.0f; acc[i][1] = 0.0f; }

  // Prefetch first chunk into registers
  float rh[8], rw[4];
#pragma unroll
  for (int i = 0; i < 8; i++) rh[i] = A[(lr + 8 * i) * lda + lk];
#pragma unroll
  for (int i = 0; i < 4; i++) rw[i] = W[(nb + lr + 8 * i) * K + lk];

  for (int k0 = 0; k0 < K; k0 += 32) {
    // regs -> smem (transposed)
#pragma unroll
    for (int i = 0; i < 8; i++) hs[lk][lr + 8 * i] = rh[i];
#pragma unroll
    for (int i = 0; i < 4; i++) ws[lk][lr + 8 * i] = rw[i];
    __syncthreads();

    // prefetch next chunk while computing this one
    int k1 = k0 + 32;
    if (k1 < K) {
#pragma unroll
      for (int i = 0; i < 8; i++) rh[i] = A[(lr + 8 * i) * lda + k1 + lk];
#pragma unroll
      for (int i = 0; i < 4; i++) rw[i] = W[(nb + lr + 8 * i) * K + k1 + lk];
    }

#pragma unroll
    for (int k = 0; k < 32; k++) {
      float4 hv = *(const float4*)&hs[k][ty * 4];  // broadcast within half-warp
      float2 wv = *(const float2*)&ws[k][tx * 2];  // 128B-contiguous across lanes
      acc[0][0] += hv.x * wv.x; acc[0][1] += hv.x * wv.y;
      acc[1][0] += hv.y * wv.x; acc[1][1] += hv.y * wv.y;
      acc[2][0] += hv.z * wv.x; acc[2][1] += hv.z * wv.y;
      acc[3][0] += hv.w * wv.x; acc[3][1] += hv.w * wv.y;
    }
    __syncthreads();
  }

  const int m0 = ty * 4;
  if (MODE == 0) {
#pragma unroll
    for (int i = 0; i < 4; i++)
#pragma unroll
      for (int j = 0; j < 2; j++)
        d_h0[(m0 + i) * NG + nb + tx * 2 + j] = acc[i][j];
  } else if (MODE == 1) {
    // Fused RNN epilogue. Effective constants (names swapped in the module):
    //   z -= 0.1 * va_old;  va_new = va_old + 0.9 * (zp_old - va_old);  zp_new = z
#pragma unroll
    for (int i = 0; i < 4; i++) {
      int m = m0 + i;
      float v0 = v[(m * TT + t) * 2 + 0];
      float v1 = v[(m * TT + t) * 2 + 1];
#pragma unroll
      for (int j = 0; j < 2; j++) {
        int n = nb + tx * 2 + j;
        float z = acc[i][j] + v0 * Wih[n * 2 + 0] + v1 * Wih[n * 2 + 1];
        int idx = m * NG + n;
        float va = d_va[idx];
        float zp = d_zp[idx];
        z -= 0.1f * va;
        d_va[idx] = va + 0.9f * (zp - va);
        d_zp[idx] = z;
        d_g[(m * TT + t) * NG + n] = fmaxf(z, 0.0f);
      }
    }
  } else {
    int mg = blockIdx.y * 64 + m0;
#pragma unroll
    for (int i = 0; i < 4; i++)
#pragma unroll
      for (int j = 0; j < 2; j++)
        outp[(size_t)(mg + i) * NP + nb + tx * 2 + j] = acc[i][j];
  }
}

extern "C" void kernel_launch(void* const* d_in, const int* in_sizes, int n_in,
                              void* d_out, int out_size) {
  // Input order per reference setup_inputs():
  //   v [64,100,2], p0 [64,512], W_init [4096,512], W_ih [4096,2],
  //   W_hh [4096,4096], W_dec [512,4096]
  const float* v      = (const float*)d_in[0];
  const float* p0     = (const float*)d_in[1];
  const float* W_init = (const float*)d_in[2];
  const float* W_ih   = (const float*)d_in[3];
  const float* W_hh   = (const float*)d_in[4];
  const float* W_dec  = (const float*)d_in[5];
  float* out = (float*)d_out;

  // 1) reset va / zp
  zero_state_kernel<<<128, 256>>>();

  // 2) h0 = p0 @ W_init^T
  gemm_kernel<0><<<dim3(NG / 32, 1), 256>>>(p0, W_init, nullptr, nullptr, nullptr, NP, 0);

  // 3) 100 sequential recurrence steps (each: GEMM + fused epilogue)
  for (int t = 0; t < TT; t++)
    gemm_kernel<1><<<dim3(NG / 32, 1), 256>>>(nullptr, W_hh, v, W_ih, nullptr, NG, t);

  // 4) decode: out[6400, 512] = g[6400, 4096] @ W_dec^T
  gemm_kernel<2><<<dim3(NP / 32, (BB * TT) / 64), 256>>>(nullptr, W_dec, nullptr, nullptr, out, NG, 0);
}

// round 5
// speedup vs baseline: 2.6836x; 2.6836x over previous
#include <cuda_runtime.h>
#include <cuda_bf16.h>
#include <cstdint>

// SorscherRNN via warp-level mma.sync (bf16x3 hi/lo split == fp32-class accuracy).
// tcgen05 is unavailable: harness PTX target is plain sm_103 (no 'a' features).
//   h0 = p0 @ W_init^T
//   t = 0..99: z = v_t@W_ih^T + h@W_hh^T - 0.1*va; va += 0.9*(zp - va); zp = z; h = relu(z)
//   out = g @ W_dec^T
// B=64, T=100, NG=4096, NP=512.

#define NG 4096
#define NP 512
#define BB 64
#define TT 100
#define KC 64        // K elements per stage (128 bytes of bf16 per row)
#define NSTAGE (NG / KC)

// smem layout per stage (bytes)
#define OFF_AH 0
#define OFF_AL 8192
#define OFF_WH 16384
#define OFF_WL 20480
#define STAGE_BYTES 24576
#define SMEM_TOTAL (3 * STAGE_BYTES)

// ---------------- device scratch (allocation-free) ----------------
__device__ __nv_bfloat16 d_whi[NG * NG], d_wlo[NG * NG];           // W_hh split
__device__ __nv_bfloat16 d_dhi[NP * NG], d_dlo[NP * NG];           // W_dec split
__device__ __nv_bfloat16 d_ghi[BB * TT * NG], d_glo[BB * TT * NG]; // relu outputs split
__device__ __nv_bfloat16 d_h0hi[BB * NG], d_h0lo[BB * NG];
__device__ float d_va[BB * NG], d_zp[BB * NG];

// ---------------- helpers ----------------
__device__ __forceinline__ uint32_t smem_u32(const void* p) {
  uint32_t a;
  asm("{ .reg .u64 t; cvta.to.shared.u64 t, %1; cvt.u32.u64 %0, t; }" : "=r"(a) : "l"(p));
  return a;
}

#define CP16(dst, src) \
  asm volatile("cp.async.cg.shared.global [%0], [%1], 16;" :: "r"(dst), "l"(src) : "memory")
#define CP_COMMIT() asm volatile("cp.async.commit_group;" ::: "memory")
#define CP_WAIT1()  asm volatile("cp.async.wait_group 1;" ::: "memory")

#define LDSM4(r0, r1, r2, r3, a) \
  asm volatile("ldmatrix.sync.aligned.m8n8.x4.shared.b16 {%0,%1,%2,%3}, [%4];" \
               : "=r"(r0), "=r"(r1), "=r"(r2), "=r"(r3) : "r"(a))

#define MMA16816(d, a, b0, b1) \
  asm volatile("mma.sync.aligned.m16n8k16.row.col.f32.bf16.bf16.f32 " \
               "{%0,%1,%2,%3}, {%4,%5,%6,%7}, {%8,%9}, {%0,%1,%2,%3};" \
               : "+f"((d)[0]), "+f"((d)[1]), "+f"((d)[2]), "+f"((d)[3]) \
               : "r"((a)[0]), "r"((a)[1]), "r"((a)[2]), "r"((a)[3]), "r"(b0), "r"(b1))

// ---------------- small kernels ----------------
__global__ void zero_state_kernel() {
  int i = blockIdx.x * blockDim.x + threadIdx.x;
  int stride = gridDim.x * blockDim.x;
  for (int k = i; k < BB * NG; k += stride) { d_va[k] = 0.0f; d_zp[k] = 0.0f; }
}

template <int SEL>
__global__ void convert_kernel(const float4* __restrict__ src, int n4) {
  __nv_bfloat162* hp = (__nv_bfloat162*)((SEL == 0) ? d_whi : d_dhi);
  __nv_bfloat162* lp = (__nv_bfloat162*)((SEL == 0) ? d_wlo : d_dlo);
  int i = blockIdx.x * blockDim.x + threadIdx.x;
  int stride = gridDim.x * blockDim.x;
  for (; i < n4; i += stride) {
    float4 x = src[i];
    __nv_bfloat16 h0 = __float2bfloat16(x.x), h1 = __float2bfloat16(x.y);
    __nv_bfloat16 h2 = __float2bfloat16(x.z), h3 = __float2bfloat16(x.w);
    hp[2 * i]     = __nv_bfloat162(h0, h1);
    hp[2 * i + 1] = __nv_bfloat162(h2, h3);
    lp[2 * i]     = __nv_bfloat162(__float2bfloat16(x.x - __bfloat162float(h0)),
                                   __float2bfloat16(x.y - __bfloat162float(h1)));
    lp[2 * i + 1] = __nv_bfloat162(__float2bfloat16(x.z - __bfloat162float(h2)),
                                   __float2bfloat16(x.w - __bfloat162float(h3)));
  }
}

// h0 = p0 @ W_init^T  (fp32 SIMT, K=512) -> bf16 hi/lo split
__global__ void h0_kernel(const float* __restrict__ p0, const float* __restrict__ Wi) {
  __shared__ __align__(16) float hs[32][68];
  __shared__ __align__(16) float ws[32][34];
  const int tid = threadIdx.x;
  const int tx = tid & 15, ty = tid >> 4, lk = tid & 31, lr = tid >> 5;
  const int nb = blockIdx.x * 32;
  float acc[4][2];
#pragma unroll
  for (int i = 0; i < 4; i++) { acc[i][0] = 0.f; acc[i][1] = 0.f; }
  float rh[8], rw[4];
#pragma unroll
  for (int i = 0; i < 8; i++) rh[i] = p0[(lr + 8 * i) * NP + lk];
#pragma unroll
  for (int i = 0; i < 4; i++) rw[i] = Wi[(nb + lr + 8 * i) * NP + lk];
  for (int k0 = 0; k0 < NP; k0 += 32) {
#pragma unroll
    for (int i = 0; i < 8; i++) hs[lk][lr + 8 * i] = rh[i];
#pragma unroll
    for (int i = 0; i < 4; i++) ws[lk][lr + 8 * i] = rw[i];
    __syncthreads();
    int k1 = k0 + 32;
    if (k1 < NP) {
#pragma unroll
      for (int i = 0; i < 8; i++) rh[i] = p0[(lr + 8 * i) * NP + k1 + lk];
#pragma unroll
      for (int i = 0; i < 4; i++) rw[i] = Wi[(nb + lr + 8 * i) * NP + k1 + lk];
    }
#pragma unroll
    for (int k = 0; k < 32; k++) {
      float4 hv = *(const float4*)&hs[k][ty * 4];
      float2 wv = *(const float2*)&ws[k][tx * 2];
      acc[0][0] += hv.x * wv.x; acc[0][1] += hv.x * wv.y;
      acc[1][0] += hv.y * wv.x; acc[1][1] += hv.y * wv.y;
      acc[2][0] += hv.z * wv.x; acc[2][1] += hv.z * wv.y;
      acc[3][0] += hv.w * wv.x; acc[3][1] += hv.w * wv.y;
    }
    __syncthreads();
  }
  const int m0 = ty * 4;
#pragma unroll
  for (int i = 0; i < 4; i++)
#pragma unroll
    for (int j = 0; j < 2; j++) {
      float s = acc[i][j];
      int m = m0 + i, n = nb + tx * 2 + j;
      __nv_bfloat16 h = __float2bfloat16(s);
      d_h0hi[m * NG + n] = h;
      d_h0lo[m * NG + n] = __float2bfloat16(s - __bfloat162float(h));
    }
}

// ---------------- main mma.sync GEMM ----------------
// D[64 x 32-tile] = bf16x3( A[64,4096] , B[32-tile,4096]^T )
// EPI=1: RNN step with fused epilogue. EPI=2: decode, plain fp32 store.
// 256 threads = 8 warps: warp (wm = w&3, wn = w>>2) owns an m16 x n16 tile.
template <int EPI>
__global__ void __launch_bounds__(256, 1) mma_gemm(
    const float* __restrict__ v, const float* __restrict__ Wih,
    float* __restrict__ outp, int t) {
  extern __shared__ __align__(1024) char smem[];
  const uint32_t sb = smem_u32(smem);

  const int tid = threadIdx.x;
  const int nb = blockIdx.x * 32;
  const long mbase = (EPI == 2) ? (long)blockIdx.y * 64 : 0;

  const __nv_bfloat16 *Ahi, *Alo, *Bh, *Bl;
  long lda;
  if constexpr (EPI == 1) {
    Bh = d_whi; Bl = d_wlo;
    if (t == 0) { Ahi = d_h0hi; Alo = d_h0lo; lda = NG; }
    else {
      Ahi = d_ghi + (long)(t - 1) * NG;  // row m -> g[m][t-1][:]
      Alo = d_glo + (long)(t - 1) * NG;
      lda = (long)TT * NG;
    }
  } else {
    Bh = d_dhi; Bl = d_dlo;
    Ahi = d_ghi + mbase * NG;  // g as [6400, 4096]
    Alo = d_glo + mbase * NG;
    lda = NG;
  }

  // ---- loader setup: 6 x 16B cp.async per thread per stage ----
  unsigned long long srcs[6];
  uint32_t offs[6];
#pragma unroll
  for (int i = 0; i < 6; i++) {
    int q = tid + i * 256;
    const __nv_bfloat16* src;
    int r, ch;
    uint32_t base;
    if (q < 512)       { r = q >> 3;            ch = q & 7; src = Ahi + (long)r * lda + ch * 8;        base = OFF_AH; }
    else if (q < 1024) { r = (q - 512) >> 3;    ch = q & 7; src = Alo + (long)r * lda + ch * 8;        base = OFF_AL; }
    else if (q < 1280) { r = (q - 1024) >> 3;   ch = q & 7; src = Bh + (long)(nb + r) * NG + ch * 8;   base = OFF_WH; }
    else               { r = (q - 1280) >> 3;   ch = q & 7; src = Bl + (long)(nb + r) * NG + ch * 8;   base = OFF_WL; }
    srcs[i] = (unsigned long long)__cvta_generic_to_global(src);
    offs[i] = base + r * 128 + ((uint32_t)(ch ^ (r & 7)) << 4);
  }

  // ---- compute-side constants ----
  const int lane = tid & 31, warp = tid >> 5;
  const int wm = warp & 3, wn = warp >> 2;
  const int rowA = wm * 16 + (lane & 15);
  const int rowB = wn * 16 + (lane & 15);
  const int halfk = lane >> 4;
  const uint32_t aAh = rowA * 128, aB = rowB * 128;
  const uint32_t swA = (uint32_t)(rowA & 7), swB = (uint32_t)(rowB & 7);

  float acc[2][4];
#pragma unroll
  for (int i = 0; i < 2; i++)
#pragma unroll
    for (int j = 0; j < 4; j++) acc[i][j] = 0.0f;

  // prologue: stages 0, 1
#pragma unroll
  for (int s = 0; s < 2; s++) {
    const uint32_t dbase = sb + s * STAGE_BYTES;
#pragma unroll
    for (int i = 0; i < 6; i++) { CP16(dbase + offs[i], srcs[i]); srcs[i] += KC * 2; }
    CP_COMMIT();
  }

  for (int s = 0; s < NSTAGE; s++) {
    CP_WAIT1();
    __syncthreads();

    if (s + 2 < NSTAGE) {
      const uint32_t dbase = sb + ((s + 2) % 3) * STAGE_BYTES;
#pragma unroll
      for (int i = 0; i < 6; i++) { CP16(dbase + offs[i], srcs[i]); srcs[i] += KC * 2; }
    }
    CP_COMMIT();

    const uint32_t st = sb + (s % 3) * STAGE_BYTES;
#pragma unroll
    for (int k16 = 0; k16 < 4; k16++) {
      const uint32_t ch = (uint32_t)(k16 * 2 + halfk);
      uint32_t ah[4], al[4], bh[4], bl[4];
      LDSM4(ah[0], ah[1], ah[2], ah[3], st + OFF_AH + aAh + ((ch ^ swA) << 4));
      LDSM4(al[0], al[1], al[2], al[3], st + OFF_AL + aAh + ((ch ^ swA) << 4));
      LDSM4(bh[0], bh[1], bh[2], bh[3], st + OFF_WH + aB + ((ch ^ swB) << 4));
      LDSM4(bl[0], bl[1], bl[2], bl[3], st + OFF_WL + aB + ((ch ^ swB) << 4));
#pragma unroll
      for (int j = 0; j < 2; j++) {
        MMA16816(acc[j], ah, bh[j], bh[j + 2]);
        MMA16816(acc[j], ah, bl[j], bl[j + 2]);
        MMA16816(acc[j], al, bh[j], bh[j + 2]);
      }
    }
    __syncthreads();
  }

  // ---- epilogue ----
  const int r = lane >> 2, c = (lane & 3) * 2;
  if constexpr (EPI == 1) {
    const float2* wih2 = (const float2*)Wih;
#pragma unroll
    for (int rr = 0; rr < 2; rr++) {
      const int m = wm * 16 + r + rr * 8;
      const float v0 = v[(m * TT + t) * 2 + 0];
      const float v1 = v[(m * TT + t) * 2 + 1];
      const long grow = ((long)m * TT + t) * NG;
#pragma unroll
      for (int j2 = 0; j2 < 2; j2++) {
#pragma unroll
        for (int jj = 0; jj < 2; jj++) {
          const int n = nb + wn * 16 + j2 * 8 + c + jj;
          float2 w = wih2[n];
          float z = acc[j2][rr * 2 + jj] + v0 * w.x + v1 * w.y;
          const int idx = m * NG + n;
          float va = d_va[idx], zp = d_zp[idx];
          z -= 0.1f * va;
          d_va[idx] = va + 0.9f * (zp - va);
          d_zp[idx] = z;
          float sg = fmaxf(z, 0.0f);
          __nv_bfloat16 h = __float2bfloat16(sg);
          d_ghi[grow + n] = h;
          d_glo[grow + n] = __float2bfloat16(sg - __bfloat162float(h));
        }
      }
    }
  } else {
#pragma unroll
    for (int rr = 0; rr < 2; rr++) {
      const long m = mbase + wm * 16 + r + rr * 8;
#pragma unroll
      for (int j2 = 0; j2 < 2; j2++) {
        const int n = nb + wn * 16 + j2 * 8 + c;
        *(float2*)&outp[m * NP + n] = make_float2(acc[j2][rr * 2 + 0], acc[j2][rr * 2 + 1]);
      }
    }
  }
}

// ---------------- launch ----------------
extern "C" void kernel_launch(void* const* d_in, const int* in_sizes, int n_in,
                              void* d_out, int out_size) {
  const float* v      = (const float*)d_in[0];
  const float* p0     = (const float*)d_in[1];
  const float* W_init = (const float*)d_in[2];
  const float* W_ih   = (const float*)d_in[3];
  const float* W_hh   = (const float*)d_in[4];
  const float* W_dec  = (const float*)d_in[5];
  float* out = (float*)d_out;

  static bool attr_done = false;
  if (!attr_done) {
    cudaFuncSetAttribute(mma_gemm<1>, cudaFuncAttributeMaxDynamicSharedMemorySize, SMEM_TOTAL);
    cudaFuncSetAttribute(mma_gemm<2>, cudaFuncAttributeMaxDynamicSharedMemorySize, SMEM_TOTAL);
    attr_done = true;
  }

  // per-call prep (deterministic across graph replays)
  convert_kernel<0><<<2048, 256>>>((const float4*)W_hh, NG * NG / 4);
  convert_kernel<1><<<512, 256>>>((const float4*)W_dec, NP * NG / 4);
  zero_state_kernel<<<128, 256>>>();
  h0_kernel<<<128, 256>>>(p0, W_init);

  // 100 sequential recurrence steps on HMMA tensor path
  for (int t = 0; t < TT; t++)
    mma_gemm<1><<<128, 256, SMEM_TOTAL>>>(v, W_ih, nullptr, t);

  // decode: out[6400,512] = g[6400,4096] @ W_dec^T
  mma_gemm<2><<<dim3(NP / 32, (BB * TT) / 64), 256, SMEM_TOTAL>>>(nullptr, nullptr, out, 0);
}

// round 7
// speedup vs baseline: 2.7776x; 1.0350x over previous
#include <cuda_runtime.h>
#include <cuda_bf16.h>
#include <cstdint>

// SorscherRNN via warp-level mma.sync (bf16x3 hi/lo split == fp32-class accuracy).
// tcgen05 unavailable (harness PTX target is plain sm_103).
// R7 = R5 + 6 independent MMA accumulator chains + 4-stage pipeline (1 sync/stage).
// R6's createpolicy/L2::cache_hint and st.global.cs trapped (illegal instruction)
// on this target -> removed; plain cp.async + plain stores.

#define NG 4096
#define NP 512
#define BB 64
#define TT 100
#define KC 64        // K elements per stage (128 B of bf16 per row)
#define NSTAGE (NG / KC)

// smem layout per stage (bytes)
#define OFF_AH 0
#define OFF_AL 8192
#define OFF_WH 16384
#define OFF_WL 20480
#define STAGE_BYTES 24576
#define PIPE 4
#define SMEM_TOTAL (PIPE * STAGE_BYTES)

// ---------------- device scratch (allocation-free) ----------------
__device__ __nv_bfloat16 d_whi[NG * NG], d_wlo[NG * NG];           // W_hh split
__device__ __nv_bfloat16 d_dhi[NP * NG], d_dlo[NP * NG];           // W_dec split
__device__ __nv_bfloat16 d_ghi[BB * TT * NG], d_glo[BB * TT * NG]; // relu outputs split
__device__ __nv_bfloat16 d_h0hi[BB * NG], d_h0lo[BB * NG];
__device__ float d_va[BB * NG], d_zp[BB * NG];

// ---------------- helpers ----------------
__device__ __forceinline__ uint32_t smem_u32(const void* p) {
  uint32_t a;
  asm("{ .reg .u64 t; cvta.to.shared.u64 t, %1; cvt.u32.u64 %0, t; }" : "=r"(a) : "l"(p));
  return a;
}

#define CP16(dst, src) \
  asm volatile("cp.async.cg.shared.global [%0], [%1], 16;" :: "r"(dst), "l"(src) : "memory")
#define CP_COMMIT() asm volatile("cp.async.commit_group;" ::: "memory")
#define CP_WAIT2()  asm volatile("cp.async.wait_group 2;" ::: "memory")

#define LDSM4(r0, r1, r2, r3, a) \
  asm volatile("ldmatrix.sync.aligned.m8n8.x4.shared.b16 {%0,%1,%2,%3}, [%4];" \
               : "=r"(r0), "=r"(r1), "=r"(r2), "=r"(r3) : "r"(a))

#define MMA16816(d, a, b0, b1) \
  asm volatile("mma.sync.aligned.m16n8k16.row.col.f32.bf16.bf16.f32 " \
               "{%0,%1,%2,%3}, {%4,%5,%6,%7}, {%8,%9}, {%0,%1,%2,%3};" \
               : "+f"((d)[0]), "+f"((d)[1]), "+f"((d)[2]), "+f"((d)[3]) \
               : "r"((a)[0]), "r"((a)[1]), "r"((a)[2]), "r"((a)[3]), "r"(b0), "r"(b1))

// ---------------- small kernels ----------------
__global__ void zero_state_kernel() {
  int i = blockIdx.x * blockDim.x + threadIdx.x;
  int stride = gridDim.x * blockDim.x;
  for (int k = i; k < BB * NG; k += stride) { d_va[k] = 0.0f; d_zp[k] = 0.0f; }
}

template <int SEL>
__global__ void convert_kernel(const float4* __restrict__ src, int n4) {
  __nv_bfloat162* hp = (__nv_bfloat162*)((SEL == 0) ? d_whi : d_dhi);
  __nv_bfloat162* lp = (__nv_bfloat162*)((SEL == 0) ? d_wlo : d_dlo);
  int i = blockIdx.x * blockDim.x + threadIdx.x;
  int stride = gridDim.x * blockDim.x;
  for (; i < n4; i += stride) {
    float4 x = src[i];
    __nv_bfloat16 h0 = __float2bfloat16(x.x), h1 = __float2bfloat16(x.y);
    __nv_bfloat16 h2 = __float2bfloat16(x.z), h3 = __float2bfloat16(x.w);
    hp[2 * i]     = __nv_bfloat162(h0, h1);
    hp[2 * i + 1] = __nv_bfloat162(h2, h3);
    lp[2 * i]     = __nv_bfloat162(__float2bfloat16(x.x - __bfloat162float(h0)),
                                   __float2bfloat16(x.y - __bfloat162float(h1)));
    lp[2 * i + 1] = __nv_bfloat162(__float2bfloat16(x.z - __bfloat162float(h2)),
                                   __float2bfloat16(x.w - __bfloat162float(h3)));
  }
}

// h0 = p0 @ W_init^T  (fp32 SIMT, K=512) -> bf16 hi/lo split
__global__ void h0_kernel(const float* __restrict__ p0, const float* __restrict__ Wi) {
  __shared__ __align__(16) float hs[32][68];
  __shared__ __align__(16) float ws[32][34];
  const int tid = threadIdx.x;
  const int tx = tid & 15, ty = tid >> 4, lk = tid & 31, lr = tid >> 5;
  const int nb = blockIdx.x * 32;
  float acc[4][2];
#pragma unroll
  for (int i = 0; i < 4; i++) { acc[i][0] = 0.f; acc[i][1] = 0.f; }
  float rh[8], rw[4];
#pragma unroll
  for (int i = 0; i < 8; i++) rh[i] = p0[(lr + 8 * i) * NP + lk];
#pragma unroll
  for (int i = 0; i < 4; i++) rw[i] = Wi[(nb + lr + 8 * i) * NP + lk];
  for (int k0 = 0; k0 < NP; k0 += 32) {
#pragma unroll
    for (int i = 0; i < 8; i++) hs[lk][lr + 8 * i] = rh[i];
#pragma unroll
    for (int i = 0; i < 4; i++) ws[lk][lr + 8 * i] = rw[i];
    __syncthreads();
    int k1 = k0 + 32;
    if (k1 < NP) {
#pragma unroll
      for (int i = 0; i < 8; i++) rh[i] = p0[(lr + 8 * i) * NP + k1 + lk];
#pragma unroll
      for (int i = 0; i < 4; i++) rw[i] = Wi[(nb + lr + 8 * i) * NP + k1 + lk];
    }
#pragma unroll
    for (int k = 0; k < 32; k++) {
      float4 hv = *(const float4*)&hs[k][ty * 4];
      float2 wv = *(const float2*)&ws[k][tx * 2];
      acc[0][0] += hv.x * wv.x; acc[0][1] += hv.x * wv.y;
      acc[1][0] += hv.y * wv.x; acc[1][1] += hv.y * wv.y;
      acc[2][0] += hv.z * wv.x; acc[2][1] += hv.z * wv.y;
      acc[3][0] += hv.w * wv.x; acc[3][1] += hv.w * wv.y;
    }
    __syncthreads();
  }
  const int m0 = ty * 4;
#pragma unroll
  for (int i = 0; i < 4; i++)
#pragma unroll
    for (int j = 0; j < 2; j++) {
      float s = acc[i][j];
      int m = m0 + i, n = nb + tx * 2 + j;
      __nv_bfloat16 h = __float2bfloat16(s);
      d_h0hi[m * NG + n] = h;
      d_h0lo[m * NG + n] = __float2bfloat16(s - __bfloat162float(h));
    }
}

// ---------------- main mma.sync GEMM ----------------
// D[64 x 32-tile] = bf16x3( A[64,4096] , B[32-tile,4096]^T )
// EPI=1: RNN step with fused epilogue. EPI=2: decode, plain fp32 store.
// 256 threads = 8 warps: warp (wm = w&3, wn = w>>2) owns an m16 x n16 tile.
template <int EPI>
__global__ void __launch_bounds__(256, 1) mma_gemm(
    const float* __restrict__ v, const float* __restrict__ Wih,
    float* __restrict__ outp, int t) {
  extern __shared__ __align__(1024) char smem[];
  const uint32_t sb = smem_u32(smem);

  const int tid = threadIdx.x;
  const int nb = blockIdx.x * 32;
  const long mbase = (EPI == 2) ? (long)blockIdx.y * 64 : 0;

  const __nv_bfloat16 *Ahi, *Alo, *Bh, *Bl;
  long lda;
  if constexpr (EPI == 1) {
    Bh = d_whi; Bl = d_wlo;
    if (t == 0) { Ahi = d_h0hi; Alo = d_h0lo; lda = NG; }
    else {
      Ahi = d_ghi + (long)(t - 1) * NG;  // row m -> g[m][t-1][:]
      Alo = d_glo + (long)(t - 1) * NG;
      lda = (long)TT * NG;
    }
  } else {
    Bh = d_dhi; Bl = d_dlo;
    Ahi = d_ghi + mbase * NG;  // g as [6400, 4096]
    Alo = d_glo + mbase * NG;
    lda = NG;
  }

  // ---- loader setup: 6 x 16B cp.async per thread per stage ----
  unsigned long long srcs[6];
  uint32_t offs[6];
#pragma unroll
  for (int i = 0; i < 6; i++) {
    int q = tid + i * 256;
    const __nv_bfloat16* src;
    int r, ch;
    uint32_t base;
    if (q < 512)       { r = q >> 3;          ch = q & 7; src = Ahi + (long)r * lda + ch * 8;      base = OFF_AH; }
    else if (q < 1024) { r = (q - 512) >> 3;  ch = q & 7; src = Alo + (long)r * lda + ch * 8;      base = OFF_AL; }
    else if (q < 1280) { r = (q - 1024) >> 3; ch = q & 7; src = Bh + (long)(nb + r) * NG + ch * 8; base = OFF_WH; }
    else               { r = (q - 1280) >> 3; ch = q & 7; src = Bl + (long)(nb + r) * NG + ch * 8; base = OFF_WL; }
    srcs[i] = (unsigned long long)__cvta_generic_to_global(src);
    offs[i] = base + r * 128 + ((uint32_t)(ch ^ (r & 7)) << 4);
  }

  // ---- compute-side constants ----
  const int lane = tid & 31, warp = tid >> 5;
  const int wm = warp & 3, wn = warp >> 2;
  const int rowA = wm * 16 + (lane & 15);
  const int rowB = wn * 16 + (lane & 15);
  const int halfk = lane >> 4;
  const uint32_t aAh = rowA * 128, aB = rowB * 128;
  const uint32_t swA = (uint32_t)(rowA & 7), swB = (uint32_t)(rowB & 7);

  // 6 independent accumulator chains: {hh, hl, lh} x {n-slot 0, 1}
  float ahh[2][4], ahl[2][4], alh[2][4];
#pragma unroll
  for (int j = 0; j < 2; j++)
#pragma unroll
    for (int i = 0; i < 4; i++) { ahh[j][i] = 0.f; ahl[j][i] = 0.f; alh[j][i] = 0.f; }

  // prologue: stages 0..2
#pragma unroll
  for (int s = 0; s < PIPE - 1; s++) {
    const uint32_t dbase = sb + s * STAGE_BYTES;
#pragma unroll
    for (int i = 0; i < 6; i++) { CP16(dbase + offs[i], srcs[i]); srcs[i] += KC * 2; }
    CP_COMMIT();
  }

  for (int s = 0; s < NSTAGE; s++) {
    CP_WAIT2();
    __syncthreads();

    if (s + PIPE - 1 < NSTAGE) {
      const uint32_t dbase = sb + ((s + PIPE - 1) % PIPE) * STAGE_BYTES;
#pragma unroll
      for (int i = 0; i < 6; i++) { CP16(dbase + offs[i], srcs[i]); srcs[i] += KC * 2; }
    }
    CP_COMMIT();

    const uint32_t st = sb + (s % PIPE) * STAGE_BYTES;
#pragma unroll
    for (int k16 = 0; k16 < 4; k16++) {
      const uint32_t ch = (uint32_t)(k16 * 2 + halfk);
      uint32_t ah[4], al[4], bh[4], bl[4];
      LDSM4(ah[0], ah[1], ah[2], ah[3], st + OFF_AH + aAh + ((ch ^ swA) << 4));
      LDSM4(al[0], al[1], al[2], al[3], st + OFF_AL + aAh + ((ch ^ swA) << 4));
      LDSM4(bh[0], bh[1], bh[2], bh[3], st + OFF_WH + aB + ((ch ^ swB) << 4));
      LDSM4(bl[0], bl[1], bl[2], bl[3], st + OFF_WL + aB + ((ch ^ swB) << 4));
      // 6 independent MMAs per k16 (no intra-k16 dependency)
      MMA16816(ahh[0], ah, bh[0], bh[2]);
      MMA16816(ahh[1], ah, bh[1], bh[3]);
      MMA16816(ahl[0], ah, bl[0], bl[2]);
      MMA16816(ahl[1], ah, bl[1], bl[3]);
      MMA16816(alh[0], al, bh[0], bh[2]);
      MMA16816(alh[1], al, bh[1], bh[3]);
    }
  }

  // combine chains
  float acc[2][4];
#pragma unroll
  for (int j = 0; j < 2; j++)
#pragma unroll
    for (int i = 0; i < 4; i++) acc[j][i] = ahh[j][i] + ahl[j][i] + alh[j][i];

  // ---- epilogue ----
  const int r = lane >> 2, c = (lane & 3) * 2;
  if constexpr (EPI == 1) {
    const float2* wih2 = (const float2*)Wih;
#pragma unroll
    for (int rr = 0; rr < 2; rr++) {
      const int m = wm * 16 + r + rr * 8;
      const float v0 = v[(m * TT + t) * 2 + 0];
      const float v1 = v[(m * TT + t) * 2 + 1];
      const long grow = ((long)m * TT + t) * NG;
#pragma unroll
      for (int j2 = 0; j2 < 2; j2++) {
#pragma unroll
        for (int jj = 0; jj < 2; jj++) {
          const int n = nb + wn * 16 + j2 * 8 + c + jj;
          float2 w = wih2[n];
          float z = acc[j2][rr * 2 + jj] + v0 * w.x + v1 * w.y;
          const int idx = m * NG + n;
          float va = d_va[idx], zp = d_zp[idx];
          z -= 0.1f * va;
          d_va[idx] = va + 0.9f * (zp - va);
          d_zp[idx] = z;
          float sg = fmaxf(z, 0.0f);
          __nv_bfloat16 h = __float2bfloat16(sg);
          d_ghi[grow + n] = h;
          d_glo[grow + n] = __float2bfloat16(sg - __bfloat162float(h));
        }
      }
    }
  } else {
#pragma unroll
    for (int rr = 0; rr < 2; rr++) {
      const long m = mbase + wm * 16 + r + rr * 8;
#pragma unroll
      for (int j2 = 0; j2 < 2; j2++) {
        const int n = nb + wn * 16 + j2 * 8 + c;
        *(float2*)&outp[m * NP + n] = make_float2(acc[j2][rr * 2 + 0], acc[j2][rr * 2 + 1]);
      }
    }
  }
}

// ---------------- launch ----------------
extern "C" void kernel_launch(void* const* d_in, const int* in_sizes, int n_in,
                              void* d_out, int out_size) {
  const float* v      = (const float*)d_in[0];
  const float* p0     = (const float*)d_in[1];
  const float* W_init = (const float*)d_in[2];
  const float* W_ih   = (const float*)d_in[3];
  const float* W_hh   = (const float*)d_in[4];
  const float* W_dec  = (const float*)d_in[5];
  float* out = (float*)d_out;

  cudaFuncSetAttribute(mma_gemm<1>, cudaFuncAttributeMaxDynamicSharedMemorySize, SMEM_TOTAL);
  cudaFuncSetAttribute(mma_gemm<2>, cudaFuncAttributeMaxDynamicSharedMemorySize, SMEM_TOTAL);

  // per-call prep (deterministic across graph replays)
  convert_kernel<0><<<2048, 256>>>((const float4*)W_hh, NG * NG / 4);
  convert_kernel<1><<<512, 256>>>((const float4*)W_dec, NP * NG / 4);
  zero_state_kernel<<<128, 256>>>();
  h0_kernel<<<128, 256>>>(p0, W_init);

  // 100 sequential recurrence steps on HMMA tensor path
  for (int t = 0; t < TT; t++)
    mma_gemm<1><<<128, 256, SMEM_TOTAL>>>(v, W_ih, nullptr, t);

  // decode: out[6400,512] = g[6400,4096] @ W_dec^T
  mma_gemm<2><<<dim3(NP / 32, (BB * TT) / 64), 256, SMEM_TOTAL>>>(nullptr, nullptr, out, 0);
}

// round 9
// speedup vs baseline: 2.8206x; 1.0155x over previous
#include <cuda_runtime.h>
#include <cuda_bf16.h>
#include <cstdint>

// SorscherRNN via warp-level mma.sync, bf16x3 hi/lo split (fp32-class accuracy).
// R9 = R8 with the split-K bug fixed: the W (B-operand) loader now applies the
// k-chunk column offset acol0 (R8 loaded W columns [0,1024) for every chunk).
// Warp tile 32x32, split-K x4, fused threadfence reduction + RNN epilogue.

#define NG 4096
#define NP 512
#define BB 64
#define TT 100

// ---------------- device scratch (allocation-free) ----------------
__device__ __nv_bfloat16 d_whi[NG * NG], d_wlo[NG * NG];           // W_hh split
__device__ __nv_bfloat16 d_dhi[NP * NG], d_dlo[NP * NG];           // W_dec split
__device__ __nv_bfloat16 d_ghi[BB * TT * NG], d_glo[BB * TT * NG]; // relu outputs split
__device__ __nv_bfloat16 d_h0hi[BB * NG], d_h0lo[BB * NG];
__device__ float d_va[BB * NG], d_zp[BB * NG];
__device__ float d_part[3 * BB * NG];  // split-K partials for k-chunks 0..2
__device__ int d_cnt[64];              // per-n-tile arrival counters

// ---------------- helpers ----------------
__device__ __forceinline__ uint32_t smem_u32(const void* p) {
  uint32_t a;
  asm("{ .reg .u64 t; cvta.to.shared.u64 t, %1; cvt.u32.u64 %0, t; }" : "=r"(a) : "l"(p));
  return a;
}

#define CP16(dst, src) \
  asm volatile("cp.async.cg.shared.global [%0], [%1], 16;" :: "r"(dst), "l"(src) : "memory")
#define CP_COMMIT() asm volatile("cp.async.commit_group;" ::: "memory")
#define CP_WAIT2()  asm volatile("cp.async.wait_group 2;" ::: "memory")

#define LDSM4(r0, r1, r2, r3, a) \
  asm volatile("ldmatrix.sync.aligned.m8n8.x4.shared.b16 {%0,%1,%2,%3}, [%4];" \
               : "=r"(r0), "=r"(r1), "=r"(r2), "=r"(r3) : "r"(a))

#define MMA16816(d, a, b0, b1) \
  asm volatile("mma.sync.aligned.m16n8k16.row.col.f32.bf16.bf16.f32 " \
               "{%0,%1,%2,%3}, {%4,%5,%6,%7}, {%8,%9}, {%0,%1,%2,%3};" \
               : "+f"((d)[0]), "+f"((d)[1]), "+f"((d)[2]), "+f"((d)[3]) \
               : "r"((a)[0]), "r"((a)[1]), "r"((a)[2]), "r"((a)[3]), "r"(b0), "r"(b1))

// ---------------- small kernels ----------------
__global__ void zero_state_kernel() {
  int i = blockIdx.x * blockDim.x + threadIdx.x;
  int stride = gridDim.x * blockDim.x;
  for (int k = i; k < BB * NG; k += stride) { d_va[k] = 0.0f; d_zp[k] = 0.0f; }
  if (blockIdx.x == 0 && threadIdx.x < 64) d_cnt[threadIdx.x] = 0;
}

template <int SEL>
__global__ void convert_kernel(const float4* __restrict__ src, int n4) {
  __nv_bfloat162* hp = (__nv_bfloat162*)((SEL == 0) ? d_whi : d_dhi);
  __nv_bfloat162* lp = (__nv_bfloat162*)((SEL == 0) ? d_wlo : d_dlo);
  int i = blockIdx.x * blockDim.x + threadIdx.x;
  int stride = gridDim.x * blockDim.x;
  for (; i < n4; i += stride) {
    float4 x = src[i];
    __nv_bfloat16 h0 = __float2bfloat16(x.x), h1 = __float2bfloat16(x.y);
    __nv_bfloat16 h2 = __float2bfloat16(x.z), h3 = __float2bfloat16(x.w);
    hp[2 * i]     = __nv_bfloat162(h0, h1);
    hp[2 * i + 1] = __nv_bfloat162(h2, h3);
    lp[2 * i]     = __nv_bfloat162(__float2bfloat16(x.x - __bfloat162float(h0)),
                                   __float2bfloat16(x.y - __bfloat162float(h1)));
    lp[2 * i + 1] = __nv_bfloat162(__float2bfloat16(x.z - __bfloat162float(h2)),
                                   __float2bfloat16(x.w - __bfloat162float(h3)));
  }
}

// h0 = p0 @ W_init^T  (fp32 SIMT, K=512) -> bf16 hi/lo split
__global__ void h0_kernel(const float* __restrict__ p0, const float* __restrict__ Wi) {
  __shared__ __align__(16) float hs[32][68];
  __shared__ __align__(16) float ws[32][34];
  const int tid = threadIdx.x;
  const int tx = tid & 15, ty = tid >> 4, lk = tid & 31, lr = tid >> 5;
  const int nb = blockIdx.x * 32;
  float acc[4][2];
#pragma unroll
  for (int i = 0; i < 4; i++) { acc[i][0] = 0.f; acc[i][1] = 0.f; }
  float rh[8], rw[4];
#pragma unroll
  for (int i = 0; i < 8; i++) rh[i] = p0[(lr + 8 * i) * NP + lk];
#pragma unroll
  for (int i = 0; i < 4; i++) rw[i] = Wi[(nb + lr + 8 * i) * NP + lk];
  for (int k0 = 0; k0 < NP; k0 += 32) {
#pragma unroll
    for (int i = 0; i < 8; i++) hs[lk][lr + 8 * i] = rh[i];
#pragma unroll
    for (int i = 0; i < 4; i++) ws[lk][lr + 8 * i] = rw[i];
    __syncthreads();
    int k1 = k0 + 32;
    if (k1 < NP) {
#pragma unroll
      for (int i = 0; i < 8; i++) rh[i] = p0[(lr + 8 * i) * NP + k1 + lk];
#pragma unroll
      for (int i = 0; i < 4; i++) rw[i] = Wi[(nb + lr + 8 * i) * NP + k1 + lk];
    }
#pragma unroll
    for (int k = 0; k < 32; k++) {
      float4 hv = *(const float4*)&hs[k][ty * 4];
      float2 wv = *(const float2*)&ws[k][tx * 2];
      acc[0][0] += hv.x * wv.x; acc[0][1] += hv.x * wv.y;
      acc[1][0] += hv.y * wv.x; acc[1][1] += hv.y * wv.y;
      acc[2][0] += hv.z * wv.x; acc[2][1] += hv.z * wv.y;
      acc[3][0] += hv.w * wv.x; acc[3][1] += hv.w * wv.y;
    }
    __syncthreads();
  }
  const int m0 = ty * 4;
#pragma unroll
  for (int i = 0; i < 4; i++)
#pragma unroll
    for (int j = 0; j < 2; j++) {
      float s = acc[i][j];
      int m = m0 + i, n = nb + tx * 2 + j;
      __nv_bfloat16 h = __float2bfloat16(s);
      d_h0hi[m * NG + n] = h;
      d_h0lo[m * NG + n] = __float2bfloat16(s - __bfloat162float(h));
    }
}

// ---------------- main mma.sync GEMM (warp tile 32x32) ----------------
// EPI=1: RNN step, split-K x4: grid (NG/NT, 4); k-chunks 0-2 store partials,
//        k-chunk 3 reduces + fused RNN epilogue.
// EPI=2: decode, grid (NP/NT, M/MR), plain fp32 store.
// 8 warps, warp grid WM x WN (WM = MR/32), warp tile m32 x n32.
template <int MR, int NT, int KCH, int EPI>
__global__ void __launch_bounds__(256, 1) mma_gemm(
    const float* __restrict__ v, const float* __restrict__ Wih,
    float* __restrict__ outp, int t) {
  constexpr int WM = MR / 32;
  constexpr int WN = 8 / WM;
  static_assert(NT == WN * 32, "tile mismatch");
  constexpr int NSTG = KCH / 64;
  constexpr uint32_t OAL = (uint32_t)MR * 128;
  constexpr uint32_t OWH = 2u * MR * 128;
  constexpr uint32_t OWL = 2u * MR * 128 + (uint32_t)NT * 128;
  constexpr uint32_t STG = (2u * MR + 2u * NT) * 128;  // 48 KB
  constexpr int NL = (MR + NT) / 16;                    // 12

  extern __shared__ __align__(1024) char smem[];
  const uint32_t sb = smem_u32(smem);
  const int tid = threadIdx.x;
  const int bx = blockIdx.x, by = blockIdx.y;
  const int nb = bx * NT;
  const long arow0 = (EPI == 2) ? (long)by * MR : 0;
  const long acol0 = (EPI == 1) ? (long)by * KCH : 0;

  const __nv_bfloat16 *Ahi, *Alo, *Bh, *Bl;
  long lda;
  if constexpr (EPI == 1) {
    Bh = d_whi; Bl = d_wlo;
    if (t == 0) { Ahi = d_h0hi; Alo = d_h0lo; lda = NG; }
    else {
      Ahi = d_ghi + (long)(t - 1) * NG;  // row m -> g[m][t-1][:]
      Alo = d_glo + (long)(t - 1) * NG;
      lda = (long)TT * NG;
    }
  } else {
    Bh = d_dhi; Bl = d_dlo;
    Ahi = d_ghi; Alo = d_glo; lda = NG;  // g as [6400, 4096]
  }

  // ---- loader setup: NL x 16B cp.async per thread per stage ----
  // NOTE: both A and B advance from column acol0 (the R8 bug was missing acol0 on B).
  unsigned long long srcs[NL];
  uint32_t offs[NL];
#pragma unroll
  for (int i = 0; i < NL; i++) {
    int q = tid + i * 256;
    int ch = q & 7;
    int r;
    uint32_t base;
    const __nv_bfloat16* p;
    if (q < MR * 8)                 { r = q >> 3;                      base = 0;   p = Ahi + (arow0 + r) * lda + acol0 + ch * 8; }
    else if (q < MR * 16)           { r = (q - MR * 8) >> 3;           base = OAL; p = Alo + (arow0 + r) * lda + acol0 + ch * 8; }
    else if (q < MR * 16 + NT * 8)  { r = (q - MR * 16) >> 3;          base = OWH; p = Bh + (long)(nb + r) * NG + acol0 + ch * 8; }
    else                            { r = (q - MR * 16 - NT * 8) >> 3; base = OWL; p = Bl + (long)(nb + r) * NG + acol0 + ch * 8; }
    srcs[i] = (unsigned long long)__cvta_generic_to_global(p);
    offs[i] = base + (uint32_t)r * 128 + ((uint32_t)(ch ^ (r & 7)) << 4);
  }

  // ---- compute-side constants ----
  const int lane = tid & 31, warp = tid >> 5;
  const int wm = warp % WM, wn = warp / WM;
  const int mA0 = wm * 32 + (lane & 15);
  const int nB0 = wn * 32 + (lane & 15);
  const int halfk = lane >> 4;
  const uint32_t aA0 = (uint32_t)mA0 * 128, aA1 = aA0 + 16 * 128;
  const uint32_t aB0 = (uint32_t)nB0 * 128, aB1 = aB0 + 16 * 128;
  const uint32_t swA = (uint32_t)(mA0 & 7), swB = (uint32_t)(nB0 & 7);

  float acc[2][4][4];  // [m16 block][n8 slot][frag]
#pragma unroll
  for (int mi = 0; mi < 2; mi++)
#pragma unroll
    for (int sl = 0; sl < 4; sl++)
#pragma unroll
      for (int f = 0; f < 4; f++) acc[mi][sl][f] = 0.0f;

  // prologue: 3 stages
#pragma unroll
  for (int s = 0; s < 3; s++) {
    const uint32_t db = sb + s * STG;
#pragma unroll
    for (int i = 0; i < NL; i++) { CP16(db + offs[i], srcs[i]); srcs[i] += 128; }
    CP_COMMIT();
  }

  for (int s = 0; s < NSTG; s++) {
    CP_WAIT2();
    __syncthreads();

    if (s + 3 < NSTG) {
      const uint32_t db = sb + ((s + 3) & 3) * STG;
#pragma unroll
      for (int i = 0; i < NL; i++) { CP16(db + offs[i], srcs[i]); srcs[i] += 128; }
    }
    CP_COMMIT();

    const uint32_t st = sb + (s & 3) * STG;
#pragma unroll
    for (int k16 = 0; k16 < 4; k16++) {
      const uint32_t ch = (uint32_t)(k16 * 2 + halfk);
      const uint32_t xoA = (ch ^ swA) << 4;
      const uint32_t xoB = (ch ^ swB) << 4;
      uint32_t Ah[2][4], Al[2][4], Bh_[2][4], Bl_[2][4];
      LDSM4(Ah[0][0], Ah[0][1], Ah[0][2], Ah[0][3], st + aA0 + xoA);
      LDSM4(Ah[1][0], Ah[1][1], Ah[1][2], Ah[1][3], st + aA1 + xoA);
      LDSM4(Al[0][0], Al[0][1], Al[0][2], Al[0][3], st + OAL + aA0 + xoA);
      LDSM4(Al[1][0], Al[1][1], Al[1][2], Al[1][3], st + OAL + aA1 + xoA);
      LDSM4(Bh_[0][0], Bh_[0][1], Bh_[0][2], Bh_[0][3], st + OWH + aB0 + xoB);
      LDSM4(Bh_[1][0], Bh_[1][1], Bh_[1][2], Bh_[1][3], st + OWH + aB1 + xoB);
      LDSM4(Bl_[0][0], Bl_[0][1], Bl_[0][2], Bl_[0][3], st + OWL + aB0 + xoB);
      LDSM4(Bl_[1][0], Bl_[1][1], Bl_[1][2], Bl_[1][3], st + OWL + aB1 + xoB);
#pragma unroll
      for (int mi = 0; mi < 2; mi++)
#pragma unroll
        for (int bb = 0; bb < 2; bb++)
#pragma unroll
          for (int j = 0; j < 2; j++)
            MMA16816(acc[mi][bb * 2 + j], Ah[mi], Bh_[bb][j], Bh_[bb][j + 2]);
#pragma unroll
      for (int mi = 0; mi < 2; mi++)
#pragma unroll
        for (int bb = 0; bb < 2; bb++)
#pragma unroll
          for (int j = 0; j < 2; j++)
            MMA16816(acc[mi][bb * 2 + j], Ah[mi], Bl_[bb][j], Bl_[bb][j + 2]);
#pragma unroll
      for (int mi = 0; mi < 2; mi++)
#pragma unroll
        for (int bb = 0; bb < 2; bb++)
#pragma unroll
          for (int j = 0; j < 2; j++)
            MMA16816(acc[mi][bb * 2 + j], Al[mi], Bh_[bb][j], Bh_[bb][j + 2]);
    }
  }

  const int r_ = lane >> 2, c_ = (lane & 3) * 2;

  if constexpr (EPI == 1) {
    if (by < 3) {
      // producers: write fp32 partials, then signal
      float* pp = d_part + (long)by * (BB * NG);
#pragma unroll
      for (int mi = 0; mi < 2; mi++)
#pragma unroll
        for (int bb = 0; bb < 2; bb++)
#pragma unroll
          for (int j = 0; j < 2; j++)
#pragma unroll
            for (int rr = 0; rr < 2; rr++) {
              int m = wm * 32 + mi * 16 + r_ + rr * 8;
              int n = nb + wn * 32 + bb * 16 + j * 8 + c_;
              *(float2*)&pp[m * NG + n] =
                  make_float2(acc[mi][bb * 2 + j][rr * 2], acc[mi][bb * 2 + j][rr * 2 + 1]);
            }
      __threadfence();
      __syncthreads();
      if (tid == 0) atomicAdd(&d_cnt[bx], 1);
    } else {
      // reducer (k-chunk 3): wait for 3 producers (same wave: grid 128 <= 148 SMs),
      // sum in fixed order, fused RNN epilogue. CAS(3->0) also resets for next step.
      if (tid == 0) {
        while (atomicCAS(&d_cnt[bx], 3, 0) != 3) __nanosleep(64);
      }
      __syncthreads();
      __threadfence();
      const float2* wih2 = (const float2*)Wih;
#pragma unroll
      for (int mi = 0; mi < 2; mi++)
#pragma unroll
        for (int rr = 0; rr < 2; rr++) {
          const int m = wm * 32 + mi * 16 + r_ + rr * 8;
          const float v0 = v[(m * TT + t) * 2 + 0];
          const float v1 = v[(m * TT + t) * 2 + 1];
          const long grow = ((long)m * TT + t) * NG;
#pragma unroll
          for (int bb = 0; bb < 2; bb++)
#pragma unroll
            for (int j = 0; j < 2; j++)
#pragma unroll
              for (int jj = 0; jj < 2; jj++) {
                const int n = nb + wn * 32 + bb * 16 + j * 8 + c_ + jj;
                const int idx = m * NG + n;
                float z = acc[mi][bb * 2 + j][rr * 2 + jj];
                z += d_part[idx];
                z += d_part[BB * NG + idx];
                z += d_part[2 * BB * NG + idx];
                float2 w = wih2[n];
                z += v0 * w.x + v1 * w.y;
                float va = d_va[idx], zp = d_zp[idx];
                z -= 0.1f * va;
                d_va[idx] = va + 0.9f * (zp - va);
                d_zp[idx] = z;
                float sg = fmaxf(z, 0.0f);
                __nv_bfloat16 h = __float2bfloat16(sg);
                d_ghi[grow + n] = h;
                d_glo[grow + n] = __float2bfloat16(sg - __bfloat162float(h));
              }
        }
    }
  } else {
#pragma unroll
    for (int mi = 0; mi < 2; mi++)
#pragma unroll
      for (int bb = 0; bb < 2; bb++)
#pragma unroll
        for (int j = 0; j < 2; j++)
#pragma unroll
          for (int rr = 0; rr < 2; rr++) {
            long m = arow0 + wm * 32 + mi * 16 + r_ + rr * 8;
            int n = nb + wn * 32 + bb * 16 + j * 8 + c_;
            *(float2*)&outp[m * NP + n] =
                make_float2(acc[mi][bb * 2 + j][rr * 2], acc[mi][bb * 2 + j][rr * 2 + 1]);
          }
  }
}

#define SMEM_TOT (4 * ((2 * 64 + 2 * 128) * 128))  // 4 stages x 48 KB = 192 KB

// ---------------- launch ----------------
extern "C" void kernel_launch(void* const* d_in, const int* in_sizes, int n_in,
                              void* d_out, int out_size) {
  const float* v      = (const float*)d_in[0];
  const float* p0     = (const float*)d_in[1];
  const float* W_init = (const float*)d_in[2];
  const float* W_ih   = (const float*)d_in[3];
  const float* W_hh   = (const float*)d_in[4];
  const float* W_dec  = (const float*)d_in[5];
  float* out = (float*)d_out;

  cudaFuncSetAttribute(mma_gemm<64, 128, 1024, 1>,
                       cudaFuncAttributeMaxDynamicSharedMemorySize, SMEM_TOT);
  cudaFuncSetAttribute(mma_gemm<128, 64, 4096, 2>,
                       cudaFuncAttributeMaxDynamicSharedMemorySize, SMEM_TOT);

  // per-call prep (deterministic across graph replays)
  convert_kernel<0><<<2048, 256>>>((const float4*)W_hh, NG * NG / 4);
  convert_kernel<1><<<512, 256>>>((const float4*)W_dec, NP * NG / 4);
  zero_state_kernel<<<128, 256>>>();
  h0_kernel<<<128, 256>>>(p0, W_init);

  // 100 sequential recurrence steps: split-K x4, fused reduction+epilogue
  for (int t = 0; t < TT; t++)
    mma_gemm<64, 128, 1024, 1><<<dim3(32, 4), 256, SMEM_TOT>>>(v, W_ih, nullptr, t);

  // decode: out[6400,512] = g[6400,4096] @ W_dec^T
  mma_gemm<128, 64, 4096, 2><<<dim3(NP / 64, (BB * TT) / 128), 256, SMEM_TOT>>>(
      nullptr, nullptr, out, 0);
}

// round 10
// speedup vs baseline: 3.6473x; 1.2931x over previous
#include <cuda_runtime.h>
#include <cuda_bf16.h>
#include <cstdint>

// SorscherRNN, bf16x3 hi/lo split on mma.sync.
// R10: the binding constraint was cp.async(LDGSTS) ISSUE RATE (8 cyc per 16B op
// per SMSP = ~2.1 TB/s chip ceiling; 96MB/step => ~47us). Replace per-thread
// cp.async with cp.async.bulk (2 bulk ops/stage/CTA) from PRE-TILED, pre-swizzled
// W and A layouts. mbarrier-completed 4-slot pipeline. Decode unchanged (R9).

#define NG 4096
#define NP 512
#define BB 64
#define TT 100

// step kernel tiling
#define KC 64
#define NSTG 16        // 1024 / 64 per k-chunk
#define STG_BYTES 49152u   // W 32KB (hi|lo) + A 16KB (hi|lo)
#define OWH 0u
#define OWL 16384u
#define OAH 32768u
#define OAL 40960u
#define SMEM_STEP (1024 + 4 * 49152)

// ---------------- device scratch (allocation-free) ----------------
__device__ __align__(16) unsigned char d_wtile[4ull * 32 * 16 * 32768];  // 64MB W_hh tiled hi|lo
__device__ __align__(16) unsigned char d_aslab[2ull * 4 * 16 * 16384];   // 2MB A slab, dbl-buf
__device__ __nv_bfloat16 d_dhi[NP * NG], d_dlo[NP * NG];                 // W_dec split (row-major)
__device__ __nv_bfloat16 d_ghi[BB * TT * NG], d_glo[BB * TT * NG];       // g history (for decode)
__device__ float d_va[BB * NG], d_zp[BB * NG];
__device__ float d_part[3 * BB * NG];
__device__ int d_cnt[64];

// ---------------- helpers ----------------
__device__ __forceinline__ uint32_t smem_u32(const void* p) {
  uint32_t a;
  asm("{ .reg .u64 t; cvta.to.shared.u64 t, %1; cvt.u32.u64 %0, t; }" : "=r"(a) : "l"(p));
  return a;
}

#define MBAR_INIT(a, c) asm volatile("mbarrier.init.shared.b64 [%0], %1;" :: "r"(a), "r"(c) : "memory")
#define MBAR_EXPECT_TX(a, n) \
  asm volatile("mbarrier.arrive.expect_tx.shared.b64 _, [%0], %1;" :: "r"(a), "r"(n) : "memory")
__device__ __forceinline__ void mbar_wait(uint32_t a, uint32_t par) {
  asm volatile(
      "{ .reg .pred P;\n"
      "WL%=: mbarrier.try_wait.parity.acquire.cta.shared::cta.b64 P, [%0], %1, 0x989680;\n"
      "@P bra WD%=;\n"
      "bra WL%=;\n"
      "WD%=: }"
      :: "r"(a), "r"(par) : "memory");
}
#define BULK_G2S(dst, src, sz, mb) \
  asm volatile("cp.async.bulk.shared::cta.global.mbarrier::complete_tx::bytes [%0], [%1], %2, [%3];" \
               :: "r"(dst), "l"(src), "r"(sz), "r"(mb) : "memory")

#define CP16(dst, src) \
  asm volatile("cp.async.cg.shared.global [%0], [%1], 16;" :: "r"(dst), "l"(src) : "memory")
#define CP_COMMIT() asm volatile("cp.async.commit_group;" ::: "memory")
#define CP_WAIT2()  asm volatile("cp.async.wait_group 2;" ::: "memory")

#define LDSM4(r0, r1, r2, r3, a) \
  asm volatile("ldmatrix.sync.aligned.m8n8.x4.shared.b16 {%0,%1,%2,%3}, [%4];" \
               : "=r"(r0), "=r"(r1), "=r"(r2), "=r"(r3) : "r"(a))

#define MMA16816(d, a, b0, b1) \
  asm volatile("mma.sync.aligned.m16n8k16.row.col.f32.bf16.bf16.f32 " \
               "{%0,%1,%2,%3}, {%4,%5,%6,%7}, {%8,%9}, {%0,%1,%2,%3};" \
               : "+f"((d)[0]), "+f"((d)[1]), "+f"((d)[2]), "+f"((d)[3]) \
               : "r"((a)[0]), "r"((a)[1]), "r"((a)[2]), "r"((a)[3]), "r"(b0), "r"(b1))

__device__ __forceinline__ void split2(float a, float b, uint32_t& hi, uint32_t& lo) {
  __nv_bfloat16 ha = __float2bfloat16(a), hb = __float2bfloat16(b);
  __nv_bfloat162 H(ha, hb);
  __nv_bfloat162 L(__float2bfloat16(a - __bfloat162float(ha)),
                   __float2bfloat16(b - __bfloat162float(hb)));
  hi = *(uint32_t*)&H;
  lo = *(uint32_t*)&L;
}

// ---------------- prep kernels ----------------
__global__ void zero_state_kernel() {
  int i = blockIdx.x * blockDim.x + threadIdx.x;
  int stride = gridDim.x * blockDim.x;
  for (int k = i; k < BB * NG; k += stride) { d_va[k] = 0.0f; d_zp[k] = 0.0f; }
  if (blockIdx.x == 0 && threadIdx.x < 64) d_cnt[threadIdx.x] = 0;
}

// W_hh fp32 -> tiled/swizzled bf16 hi|lo blocks (one 16B unit per iteration)
__global__ void convert_whh(const float* __restrict__ W) {
  int i = blockIdx.x * blockDim.x + threadIdx.x;
  int stride = gridDim.x * blockDim.x;
  for (; i < NG * NG / 8; i += stride) {
    int n = i >> 9, kg = i & 511;
    int k = kg << 3;
    const float4* s = (const float4*)(W + (long)n * NG + k);
    float4 x = s[0], y = s[1];
    uint4 hi, lo;
    split2(x.x, x.y, hi.x, lo.x);
    split2(x.z, x.w, hi.y, lo.y);
    split2(y.x, y.y, hi.z, lo.z);
    split2(y.z, y.w, hi.w, lo.w);
    int by = k >> 10, sg = (k & 1023) >> 6, ch = (k & 63) >> 3;
    int bx = n >> 7, r = n & 127;
    long off = (long)((by * 32 + bx) * 16 + sg) * 32768 + r * 128 + ((ch ^ (r & 7)) << 4);
    *(uint4*)(d_wtile + off) = hi;
    *(uint4*)(d_wtile + off + 16384) = lo;
  }
}

// W_dec fp32 -> row-major bf16 hi/lo (decode kernel keeps the cp.async path)
__global__ void convert_wdec(const float4* __restrict__ src, int n4) {
  __nv_bfloat162* hp = (__nv_bfloat162*)d_dhi;
  __nv_bfloat162* lp = (__nv_bfloat162*)d_dlo;
  int i = blockIdx.x * blockDim.x + threadIdx.x;
  int stride = gridDim.x * blockDim.x;
  for (; i < n4; i += stride) {
    float4 x = src[i];
    uint32_t h0, l0, h1, l1;
    split2(x.x, x.y, h0, l0);
    split2(x.z, x.w, h1, l1);
    hp[2 * i] = *(__nv_bfloat162*)&h0;
    hp[2 * i + 1] = *(__nv_bfloat162*)&h1;
    lp[2 * i] = *(__nv_bfloat162*)&l0;
    lp[2 * i + 1] = *(__nv_bfloat162*)&l1;
  }
}

// h0 = p0 @ W_init^T  -> A-slab parity 0 (tiled/swizzled hi|lo)
__global__ void h0_kernel(const float* __restrict__ p0, const float* __restrict__ Wi) {
  __shared__ __align__(16) float hs[32][68];
  __shared__ __align__(16) float ws[32][34];
  const int tid = threadIdx.x;
  const int tx = tid & 15, ty = tid >> 4, lk = tid & 31, lr = tid >> 5;
  const int nb = blockIdx.x * 32;
  float acc[4][2];
#pragma unroll
  for (int i = 0; i < 4; i++) { acc[i][0] = 0.f; acc[i][1] = 0.f; }
  float rh[8], rw[4];
#pragma unroll
  for (int i = 0; i < 8; i++) rh[i] = p0[(lr + 8 * i) * NP + lk];
#pragma unroll
  for (int i = 0; i < 4; i++) rw[i] = Wi[(nb + lr + 8 * i) * NP + lk];
  for (int k0 = 0; k0 < NP; k0 += 32) {
#pragma unroll
    for (int i = 0; i < 8; i++) hs[lk][lr + 8 * i] = rh[i];
#pragma unroll
    for (int i = 0; i < 4; i++) ws[lk][lr + 8 * i] = rw[i];
    __syncthreads();
    int k1 = k0 + 32;
    if (k1 < NP) {
#pragma unroll
      for (int i = 0; i < 8; i++) rh[i] = p0[(lr + 8 * i) * NP + k1 + lk];
#pragma unroll
      for (int i = 0; i < 4; i++) rw[i] = Wi[(nb + lr + 8 * i) * NP + k1 + lk];
    }
#pragma unroll
    for (int k = 0; k < 32; k++) {
      float4 hv = *(const float4*)&hs[k][ty * 4];
      float2 wv = *(const float2*)&ws[k][tx * 2];
      acc[0][0] += hv.x * wv.x; acc[0][1] += hv.x * wv.y;
      acc[1][0] += hv.y * wv.x; acc[1][1] += hv.y * wv.y;
      acc[2][0] += hv.z * wv.x; acc[2][1] += hv.z * wv.y;
      acc[3][0] += hv.w * wv.x; acc[3][1] += hv.w * wv.y;
    }
    __syncthreads();
  }
  const int m0 = ty * 4;
  const int n0 = nb + tx * 2;
  const int byn = n0 >> 10, sn = (n0 & 1023) >> 6, ch = (n0 & 63) >> 3;
#pragma unroll
  for (int i = 0; i < 4; i++) {
    uint32_t hi, lo;
    split2(acc[i][0], acc[i][1], hi, lo);
    int m = m0 + i;
    long off = (long)(byn * 16 + sn) * 16384 + m * 128 + ((ch ^ (m & 7)) << 4) + (n0 & 7) * 2;
    *(uint32_t*)(d_aslab + off) = hi;
    *(uint32_t*)(d_aslab + off + 8192) = lo;
  }
}

// ---------------- step kernel: bulk-fed pipeline + fused epilogue ----------------
// grid (32, 4): bx = n-tile (128 cols), by = k-chunk (1024). by 0-2 produce
// partials; by 3 reduces + RNN epilogue. 8 warps, warp tile 32x32 (2m x 4n).
__global__ void __launch_bounds__(256, 1) step_kernel(
    const float* __restrict__ v, const float* __restrict__ Wih, int t) {
  extern __shared__ __align__(1024) char smem[];
  const uint32_t sb = smem_u32(smem);
  const uint32_t mb = sb;          // 4 mbars
  const uint32_t buf = sb + 1024;
  const int tid = threadIdx.x;
  const int bx = blockIdx.x, by = blockIdx.y;
  const int nb = bx * 128;

  if (tid == 0) {
#pragma unroll
    for (int i = 0; i < 4; i++) MBAR_INIT(mb + 8 * i, 1);
  }
  __syncthreads();

  const unsigned long long wbase =
      (unsigned long long)__cvta_generic_to_global(d_wtile) +
      (unsigned long long)((by * 32 + bx) * 16) * 32768ull;
  const unsigned long long abase =
      (unsigned long long)__cvta_generic_to_global(d_aslab) +
      (unsigned long long)(((t & 1) * 4 + by) * 16) * 16384ull;

  auto issue = [&](int s) {
    const uint32_t st = buf + (uint32_t)(s & 3) * STG_BYTES;
    const uint32_t m = mb + (s & 3) * 8;
    MBAR_EXPECT_TX(m, STG_BYTES);
    BULK_G2S(st + OWH, wbase + (unsigned long long)s * 32768ull, 32768u, m);
    BULK_G2S(st + OAH, abase + (unsigned long long)s * 16384ull, 16384u, m);
  };
  if (tid == 0) { issue(0); issue(1); issue(2); }

  const int lane = tid & 31, warp = tid >> 5;
  const int wm = warp & 1, wn = warp >> 1;          // 2m x 4n warps
  const int mA0 = wm * 32 + (lane & 15);            // < 64
  const int nB0 = wn * 32 + (lane & 15);            // < 128
  const int halfk = lane >> 4;
  const uint32_t aA0 = (uint32_t)mA0 * 128, aA1 = aA0 + 16 * 128;
  const uint32_t aB0 = (uint32_t)nB0 * 128, aB1 = aB0 + 16 * 128;
  const uint32_t swA = (uint32_t)(mA0 & 7), swB = (uint32_t)(nB0 & 7);

  float acc[2][4][4];
#pragma unroll
  for (int mi = 0; mi < 2; mi++)
#pragma unroll
    for (int sl = 0; sl < 4; sl++)
#pragma unroll
      for (int f = 0; f < 4; f++) acc[mi][sl][f] = 0.0f;

  for (int s = 0; s < NSTG; s++) {
    mbar_wait(mb + (s & 3) * 8, (uint32_t)((s >> 2) & 1));
    const uint32_t st = buf + (uint32_t)(s & 3) * STG_BYTES;
#pragma unroll
    for (int k16 = 0; k16 < 4; k16++) {
      const uint32_t ch = (uint32_t)(k16 * 2 + halfk);
      const uint32_t xoA = (ch ^ swA) << 4;
      const uint32_t xoB = (ch ^ swB) << 4;
      uint32_t Ah[2][4], Al[2][4], Bh_[2][4], Bl_[2][4];
      LDSM4(Ah[0][0], Ah[0][1], Ah[0][2], Ah[0][3], st + OAH + aA0 + xoA);
      LDSM4(Ah[1][0], Ah[1][1], Ah[1][2], Ah[1][3], st + OAH + aA1 + xoA);
      LDSM4(Al[0][0], Al[0][1], Al[0][2], Al[0][3], st + OAL + aA0 + xoA);
      LDSM4(Al[1][0], Al[1][1], Al[1][2], Al[1][3], st + OAL + aA1 + xoA);
      LDSM4(Bh_[0][0], Bh_[0][1], Bh_[0][2], Bh_[0][3], st + OWH + aB0 + xoB);
      LDSM4(Bh_[1][0], Bh_[1][1], Bh_[1][2], Bh_[1][3], st + OWH + aB1 + xoB);
      LDSM4(Bl_[0][0], Bl_[0][1], Bl_[0][2], Bl_[0][3], st + OWL + aB0 + xoB);
      LDSM4(Bl_[1][0], Bl_[1][1], Bl_[1][2], Bl_[1][3], st + OWL + aB1 + xoB);
#pragma unroll
      for (int mi = 0; mi < 2; mi++)
#pragma unroll
        for (int bb = 0; bb < 2; bb++)
#pragma unroll
          for (int j = 0; j < 2; j++)
            MMA16816(acc[mi][bb * 2 + j], Ah[mi], Bh_[bb][j], Bh_[bb][j + 2]);
#pragma unroll
      for (int mi = 0; mi < 2; mi++)
#pragma unroll
        for (int bb = 0; bb < 2; bb++)
#pragma unroll
          for (int j = 0; j < 2; j++)
            MMA16816(acc[mi][bb * 2 + j], Ah[mi], Bl_[bb][j], Bl_[bb][j + 2]);
#pragma unroll
      for (int mi = 0; mi < 2; mi++)
#pragma unroll
        for (int bb = 0; bb < 2; bb++)
#pragma unroll
          for (int j = 0; j < 2; j++)
            MMA16816(acc[mi][bb * 2 + j], Al[mi], Bh_[bb][j], Bh_[bb][j + 2]);
    }
    __syncthreads();
    if (tid == 0 && s + 3 < NSTG) issue(s + 3);
  }

  const int r_ = lane >> 2, c_ = (lane & 3) * 2;

  if (by < 3) {
    float* pp = d_part + (long)by * (BB * NG);
#pragma unroll
    for (int mi = 0; mi < 2; mi++)
#pragma unroll
      for (int bb = 0; bb < 2; bb++)
#pragma unroll
        for (int j = 0; j < 2; j++)
#pragma unroll
          for (int rr = 0; rr < 2; rr++) {
            int m = wm * 32 + mi * 16 + r_ + rr * 8;
            int n = nb + wn * 32 + bb * 16 + j * 8 + c_;
            *(float2*)&pp[m * NG + n] =
                make_float2(acc[mi][bb * 2 + j][rr * 2], acc[mi][bb * 2 + j][rr * 2 + 1]);
          }
    __threadfence();
    __syncthreads();
    if (tid == 0) atomicAdd(&d_cnt[bx], 1);
  } else {
    if (tid == 0) {
      while (atomicCAS(&d_cnt[bx], 3, 0) != 3) __nanosleep(64);
    }
    __syncthreads();
    __threadfence();
    const float2* wih2 = (const float2*)Wih;
    const int p1 = (t + 1) & 1;
#pragma unroll
    for (int mi = 0; mi < 2; mi++)
#pragma unroll
      for (int rr = 0; rr < 2; rr++) {
        const int m = wm * 32 + mi * 16 + r_ + rr * 8;
        const float v0 = v[(m * TT + t) * 2 + 0];
        const float v1 = v[(m * TT + t) * 2 + 1];
        const long grow = ((long)m * TT + t) * NG;
#pragma unroll
        for (int bb = 0; bb < 2; bb++)
#pragma unroll
          for (int j = 0; j < 2; j++) {
            const int n0 = nb + wn * 32 + bb * 16 + j * 8 + c_;
            const int idx = m * NG + n0;
            float2 pa = *(const float2*)&d_part[idx];
            float2 pb = *(const float2*)&d_part[BB * NG + idx];
            float2 pc = *(const float2*)&d_part[2 * BB * NG + idx];
            float2 w0 = wih2[n0], w1 = wih2[n0 + 1];
            float z0 = acc[mi][bb * 2 + j][rr * 2] + pa.x + pb.x + pc.x + v0 * w0.x + v1 * w0.y;
            float z1 = acc[mi][bb * 2 + j][rr * 2 + 1] + pa.y + pb.y + pc.y + v0 * w1.x + v1 * w1.y;
            float2 va = *(const float2*)&d_va[idx];
            float2 zp = *(const float2*)&d_zp[idx];
            z0 -= 0.1f * va.x;
            z1 -= 0.1f * va.y;
            *(float2*)&d_va[idx] = make_float2(va.x + 0.9f * (zp.x - va.x),
                                               va.y + 0.9f * (zp.y - va.y));
            *(float2*)&d_zp[idx] = make_float2(z0, z1);
            float s0 = fmaxf(z0, 0.0f), s1 = fmaxf(z1, 0.0f);
            uint32_t hi, lo;
            split2(s0, s1, hi, lo);
            *(uint32_t*)&d_ghi[grow + n0] = hi;
            *(uint32_t*)&d_glo[grow + n0] = lo;
            const int byn = n0 >> 10, sn = (n0 & 1023) >> 6, chn = (n0 & 63) >> 3;
            long off = (long)((p1 * 4 + byn) * 16 + sn) * 16384 + m * 128 +
                       ((chn ^ (m & 7)) << 4) + (n0 & 7) * 2;
            *(uint32_t*)(d_aslab + off) = hi;
            *(uint32_t*)(d_aslab + off + 8192) = lo;
          }
      }
  }
}

// ---------------- decode (unchanged R9 structure, cp.async path) ----------------
__global__ void __launch_bounds__(256, 1) decode_gemm(float* __restrict__ outp) {
  constexpr int MR = 128, NT = 64, NSTGD = 64;
  constexpr uint32_t OAL_ = MR * 128, OWH_ = 2u * MR * 128, OWL_ = OWH_ + NT * 128;
  constexpr uint32_t STG = (2u * MR + 2u * NT) * 128;
  constexpr int NL = (MR + NT) / 16;

  extern __shared__ __align__(1024) char smem[];
  const uint32_t sb = smem_u32(smem);
  const int tid = threadIdx.x;
  const int nb = blockIdx.x * NT;
  const long arow0 = (long)blockIdx.y * MR;

  unsigned long long srcs[NL];
  uint32_t offs[NL];
#pragma unroll
  for (int i = 0; i < NL; i++) {
    int q = tid + i * 256;
    int ch = q & 7;
    int r;
    uint32_t base;
    const __nv_bfloat16* p;
    if (q < MR * 8)                 { r = q >> 3;                      base = 0;    p = d_ghi + (arow0 + r) * NG + ch * 8; }
    else if (q < MR * 16)           { r = (q - MR * 8) >> 3;           base = OAL_; p = d_glo + (arow0 + r) * NG + ch * 8; }
    else if (q < MR * 16 + NT * 8)  { r = (q - MR * 16) >> 3;          base = OWH_; p = d_dhi + (long)(nb + r) * NG + ch * 8; }
    else                            { r = (q - MR * 16 - NT * 8) >> 3; base = OWL_; p = d_dlo + (long)(nb + r) * NG + ch * 8; }
    srcs[i] = (unsigned long long)__cvta_generic_to_global(p);
    offs[i] = base + (uint32_t)r * 128 + ((uint32_t)(ch ^ (r & 7)) << 4);
  }

  const int lane = tid & 31, warp = tid >> 5;
  const int wm = warp % 4, wn = warp / 4;
  const int mA0 = wm * 32 + (lane & 15);
  const int nB0 = wn * 32 + (lane & 15);
  const int halfk = lane >> 4;
  const uint32_t aA0 = (uint32_t)mA0 * 128, aA1 = aA0 + 16 * 128;
  const uint32_t aB0 = (uint32_t)nB0 * 128, aB1 = aB0 + 16 * 128;
  const uint32_t swA = (uint32_t)(mA0 & 7), swB = (uint32_t)(nB0 & 7);

  float acc[2][4][4];
#pragma unroll
  for (int mi = 0; mi < 2; mi++)
#pragma unroll
    for (int sl = 0; sl < 4; sl++)
#pragma unroll
      for (int f = 0; f < 4; f++) acc[mi][sl][f] = 0.0f;

#pragma unroll
  for (int s = 0; s < 3; s++) {
    const uint32_t db = sb + s * STG;
#pragma unroll
    for (int i = 0; i < NL; i++) { CP16(db + offs[i], srcs[i]); srcs[i] += 128; }
    CP_COMMIT();
  }

  for (int s = 0; s < NSTGD; s++) {
    CP_WAIT2();
    __syncthreads();
    if (s + 3 < NSTGD) {
      const uint32_t db = sb + ((s + 3) & 3) * STG;
#pragma unroll
      for (int i = 0; i < NL; i++) { CP16(db + offs[i], srcs[i]); srcs[i] += 128; }
    }
    CP_COMMIT();
    const uint32_t st = sb + (s & 3) * STG;
#pragma unroll
    for (int k16 = 0; k16 < 4; k16++) {
      const uint32_t ch = (uint32_t)(k16 * 2 + halfk);
      const uint32_t xoA = (ch ^ swA) << 4;
      const uint32_t xoB = (ch ^ swB) << 4;
      uint32_t Ah[2][4], Al[2][4], Bh_[2][4], Bl_[2][4];
      LDSM4(Ah[0][0], Ah[0][1], Ah[0][2], Ah[0][3], st + aA0 + xoA);
      LDSM4(Ah[1][0], Ah[1][1], Ah[1][2], Ah[1][3], st + aA1 + xoA);
      LDSM4(Al[0][0], Al[0][1], Al[0][2], Al[0][3], st + OAL_ + aA0 + xoA);
      LDSM4(Al[1][0], Al[1][1], Al[1][2], Al[1][3], st + OAL_ + aA1 + xoA);
      LDSM4(Bh_[0][0], Bh_[0][1], Bh_[0][2], Bh_[0][3], st + OWH_ + aB0 + xoB);
      LDSM4(Bh_[1][0], Bh_[1][1], Bh_[1][2], Bh_[1][3], st + OWH_ + aB1 + xoB);
      LDSM4(Bl_[0][0], Bl_[0][1], Bl_[0][2], Bl_[0][3], st + OWL_ + aB0 + xoB);
      LDSM4(Bl_[1][0], Bl_[1][1], Bl_[1][2], Bl_[1][3], st + OWL_ + aB1 + xoB);
#pragma unroll
      for (int mi = 0; mi < 2; mi++)
#pragma unroll
        for (int bb = 0; bb < 2; bb++)
#pragma unroll
          for (int j = 0; j < 2; j++)
            MMA16816(acc[mi][bb * 2 + j], Ah[mi], Bh_[bb][j], Bh_[bb][j + 2]);
#pragma unroll
      for (int mi = 0; mi < 2; mi++)
#pragma unroll
        for (int bb = 0; bb < 2; bb++)
#pragma unroll
          for (int j = 0; j < 2; j++)
            MMA16816(acc[mi][bb * 2 + j], Ah[mi], Bl_[bb][j], Bl_[bb][j + 2]);
#pragma unroll
      for (int mi = 0; mi < 2; mi++)
#pragma unroll
        for (int bb = 0; bb < 2; bb++)
#pragma unroll
          for (int j = 0; j < 2; j++)
            MMA16816(acc[mi][bb * 2 + j], Al[mi], Bh_[bb][j], Bh_[bb][j + 2]);
    }
  }

  const int r_ = lane >> 2, c_ = (lane & 3) * 2;
#pragma unroll
  for (int mi = 0; mi < 2; mi++)
#pragma unroll
    for (int bb = 0; bb < 2; bb++)
#pragma unroll
      for (int j = 0; j < 2; j++)
#pragma unroll
        for (int rr = 0; rr < 2; rr++) {
          long m = arow0 + wm * 32 + mi * 16 + r_ + rr * 8;
          int n = nb + wn * 32 + bb * 16 + j * 8 + c_;
          *(float2*)&outp[m * NP + n] =
              make_float2(acc[mi][bb * 2 + j][rr * 2], acc[mi][bb * 2 + j][rr * 2 + 1]);
        }
}

#define SMEM_DEC (4 * ((2 * 128 + 2 * 64) * 128))

// ---------------- launch ----------------
extern "C" void kernel_launch(void* const* d_in, const int* in_sizes, int n_in,
                              void* d_out, int out_size) {
  const float* v      = (const float*)d_in[0];
  const float* p0     = (const float*)d_in[1];
  const float* W_init = (const float*)d_in[2];
  const float* W_ih   = (const float*)d_in[3];
  const float* W_hh   = (const float*)d_in[4];
  const float* W_dec  = (const float*)d_in[5];
  float* out = (float*)d_out;

  cudaFuncSetAttribute(step_kernel, cudaFuncAttributeMaxDynamicSharedMemorySize, SMEM_STEP);
  cudaFuncSetAttribute(decode_gemm, cudaFuncAttributeMaxDynamicSharedMemorySize, SMEM_DEC);

  convert_whh<<<2048, 256>>>(W_hh);
  convert_wdec<<<512, 256>>>((const float4*)W_dec, NP * NG / 4);
  zero_state_kernel<<<128, 256>>>();
  h0_kernel<<<128, 256>>>(p0, W_init);

  for (int t = 0; t < TT; t++)
    step_kernel<<<dim3(32, 4), 256, SMEM_STEP>>>(v, W_ih, t);

  decode_gemm<<<dim3(NP / 64, (BB * TT) / 128), 256, SMEM_DEC>>>(out);
}

// round 11
// speedup vs baseline: 3.7119x; 1.0177x over previous
#include <cuda_runtime.h>
#include <cuda_bf16.h>
#include <cstdint>

// SorscherRNN, bf16x3 hi/lo split on mma.sync.
// R11 = R10 + bulk-fed decode: step epilogue writes g into a persistent
// tiled/swizzled slab; W_dec pre-tiled; decode uses cp.async.bulk pipeline
// (2 bulk ops/stage) instead of 78M LDGSTS (8cyc issue each = ~550us).

#define NG 4096
#define NP 512
#define BB 64
#define TT 100

// step kernel tiling
#define NSTG 16            // 1024 / 64 per k-chunk
#define STG_BYTES 49152u   // W 32KB (hi|lo) + A 16KB (hi|lo)
#define OWH 0u
#define OWL 16384u
#define OAH 32768u
#define OAL 40960u
#define SMEM_STEP (1024 + 4 * 49152)

// decode tiling
#define DSTG 49152u        // A 32KB (hi|lo) + W 16KB (hi|lo)
#define D_OAH 0u
#define D_OAL 16384u
#define D_OWH 32768u
#define D_OWL 40960u
#define SMEM_DEC (1024 + 4 * 49152)

// ---------------- device scratch (allocation-free) ----------------
__device__ __align__(16) unsigned char d_wtile[4ull * 32 * 16 * 32768];  // 64MB W_hh tiled hi|lo
__device__ __align__(16) unsigned char d_aslab[2ull * 4 * 16 * 16384];   // 2MB A slab, dbl-buf
__device__ __align__(16) unsigned char d_gslab[50ull * 64 * 32768];      // 100MB g tiled hi|lo
__device__ __align__(16) unsigned char d_wdtile[8ull * 64 * 16384];      // 8MB W_dec tiled hi|lo
__device__ float d_va[BB * NG], d_zp[BB * NG];
__device__ float d_part[3 * BB * NG];
__device__ int d_cnt[64];

// ---------------- helpers ----------------
__device__ __forceinline__ uint32_t smem_u32(const void* p) {
  uint32_t a;
  asm("{ .reg .u64 t; cvta.to.shared.u64 t, %1; cvt.u32.u64 %0, t; }" : "=r"(a) : "l"(p));
  return a;
}

#define MBAR_INIT(a, c) asm volatile("mbarrier.init.shared.b64 [%0], %1;" :: "r"(a), "r"(c) : "memory")
#define MBAR_EXPECT_TX(a, n) \
  asm volatile("mbarrier.arrive.expect_tx.shared.b64 _, [%0], %1;" :: "r"(a), "r"(n) : "memory")
__device__ __forceinline__ void mbar_wait(uint32_t a, uint32_t par) {
  asm volatile(
      "{ .reg .pred P;\n"
      "WL%=: mbarrier.try_wait.parity.acquire.cta.shared::cta.b64 P, [%0], %1, 0x989680;\n"
      "@P bra WD%=;\n"
      "bra WL%=;\n"
      "WD%=: }"
      :: "r"(a), "r"(par) : "memory");
}
#define BULK_G2S(dst, src, sz, mb) \
  asm volatile("cp.async.bulk.shared::cta.global.mbarrier::complete_tx::bytes [%0], [%1], %2, [%3];" \
               :: "r"(dst), "l"(src), "r"(sz), "r"(mb) : "memory")

#define LDSM4(r0, r1, r2, r3, a) \
  asm volatile("ldmatrix.sync.aligned.m8n8.x4.shared.b16 {%0,%1,%2,%3}, [%4];" \
               : "=r"(r0), "=r"(r1), "=r"(r2), "=r"(r3) : "r"(a))

#define MMA16816(d, a, b0, b1) \
  asm volatile("mma.sync.aligned.m16n8k16.row.col.f32.bf16.bf16.f32 " \
               "{%0,%1,%2,%3}, {%4,%5,%6,%7}, {%8,%9}, {%0,%1,%2,%3};" \
               : "+f"((d)[0]), "+f"((d)[1]), "+f"((d)[2]), "+f"((d)[3]) \
               : "r"((a)[0]), "r"((a)[1]), "r"((a)[2]), "r"((a)[3]), "r"(b0), "r"(b1))

__device__ __forceinline__ void split2(float a, float b, uint32_t& hi, uint32_t& lo) {
  __nv_bfloat16 ha = __float2bfloat16(a), hb = __float2bfloat16(b);
  __nv_bfloat162 H(ha, hb);
  __nv_bfloat162 L(__float2bfloat16(a - __bfloat162float(ha)),
                   __float2bfloat16(b - __bfloat162float(hb)));
  hi = *(uint32_t*)&H;
  lo = *(uint32_t*)&L;
}

// ---------------- prep kernels ----------------
__global__ void zero_state_kernel() {
  int i = blockIdx.x * blockDim.x + threadIdx.x;
  int stride = gridDim.x * blockDim.x;
  for (int k = i; k < BB * NG; k += stride) { d_va[k] = 0.0f; d_zp[k] = 0.0f; }
  if (blockIdx.x == 0 && threadIdx.x < 64) d_cnt[threadIdx.x] = 0;
}

// W_hh fp32 -> tiled/swizzled bf16 hi|lo blocks
__global__ void convert_whh(const float* __restrict__ W) {
  int i = blockIdx.x * blockDim.x + threadIdx.x;
  int stride = gridDim.x * blockDim.x;
  for (; i < NG * NG / 8; i += stride) {
    int n = i >> 9, kg = i & 511;
    int k = kg << 3;
    const float4* s = (const float4*)(W + (long)n * NG + k);
    float4 x = s[0], y = s[1];
    uint4 hi, lo;
    split2(x.x, x.y, hi.x, lo.x);
    split2(x.z, x.w, hi.y, lo.y);
    split2(y.x, y.y, hi.z, lo.z);
    split2(y.z, y.w, hi.w, lo.w);
    int by = k >> 10, sg = (k & 1023) >> 6, ch = (k & 63) >> 3;
    int bx = n >> 7, r = n & 127;
    long off = (long)((by * 32 + bx) * 16 + sg) * 32768 + r * 128 + ((ch ^ (r & 7)) << 4);
    *(uint4*)(d_wtile + off) = hi;
    *(uint4*)(d_wtile + off + 16384) = lo;
  }
}

// W_dec fp32 -> tiled/swizzled bf16 hi|lo blocks (64 rows x 64 cols: 8KB hi + 8KB lo)
__global__ void convert_wdec(const float* __restrict__ W) {
  int i = blockIdx.x * blockDim.x + threadIdx.x;
  int stride = gridDim.x * blockDim.x;
  for (; i < NP * NG / 8; i += stride) {
    int n = i >> 9, kg = i & 511;
    int k = kg << 3;
    const float4* s = (const float4*)(W + (long)n * NG + k);
    float4 x = s[0], y = s[1];
    uint4 hi, lo;
    split2(x.x, x.y, hi.x, lo.x);
    split2(x.z, x.w, hi.y, lo.y);
    split2(y.x, y.y, hi.z, lo.z);
    split2(y.z, y.w, hi.w, lo.w);
    int nx = n >> 6, rn = n & 63;
    int kt = k >> 6, ch = (k & 63) >> 3;
    long off = (long)(nx * 64 + kt) * 16384 + rn * 128 + ((ch ^ (rn & 7)) << 4);
    *(uint4*)(d_wdtile + off) = hi;
    *(uint4*)(d_wdtile + off + 8192) = lo;
  }
}

// h0 = p0 @ W_init^T  -> A-slab parity 0 (tiled/swizzled hi|lo)
__global__ void h0_kernel(const float* __restrict__ p0, const float* __restrict__ Wi) {
  __shared__ __align__(16) float hs[32][68];
  __shared__ __align__(16) float ws[32][34];
  const int tid = threadIdx.x;
  const int tx = tid & 15, ty = tid >> 4, lk = tid & 31, lr = tid >> 5;
  const int nb = blockIdx.x * 32;
  float acc[4][2];
#pragma unroll
  for (int i = 0; i < 4; i++) { acc[i][0] = 0.f; acc[i][1] = 0.f; }
  float rh[8], rw[4];
#pragma unroll
  for (int i = 0; i < 8; i++) rh[i] = p0[(lr + 8 * i) * NP + lk];
#pragma unroll
  for (int i = 0; i < 4; i++) rw[i] = Wi[(nb + lr + 8 * i) * NP + lk];
  for (int k0 = 0; k0 < NP; k0 += 32) {
#pragma unroll
    for (int i = 0; i < 8; i++) hs[lk][lr + 8 * i] = rh[i];
#pragma unroll
    for (int i = 0; i < 4; i++) ws[lk][lr + 8 * i] = rw[i];
    __syncthreads();
    int k1 = k0 + 32;
    if (k1 < NP) {
#pragma unroll
      for (int i = 0; i < 8; i++) rh[i] = p0[(lr + 8 * i) * NP + k1 + lk];
#pragma unroll
      for (int i = 0; i < 4; i++) rw[i] = Wi[(nb + lr + 8 * i) * NP + k1 + lk];
    }
#pragma unroll
    for (int k = 0; k < 32; k++) {
      float4 hv = *(const float4*)&hs[k][ty * 4];
      float2 wv = *(const float2*)&ws[k][tx * 2];
      acc[0][0] += hv.x * wv.x; acc[0][1] += hv.x * wv.y;
      acc[1][0] += hv.y * wv.x; acc[1][1] += hv.y * wv.y;
      acc[2][0] += hv.z * wv.x; acc[2][1] += hv.z * wv.y;
      acc[3][0] += hv.w * wv.x; acc[3][1] += hv.w * wv.y;
    }
    __syncthreads();
  }
  const int m0 = ty * 4;
  const int n0 = nb + tx * 2;
  const int byn = n0 >> 10, sn = (n0 & 1023) >> 6, ch = (n0 & 63) >> 3;
#pragma unroll
  for (int i = 0; i < 4; i++) {
    uint32_t hi, lo;
    split2(acc[i][0], acc[i][1], hi, lo);
    int m = m0 + i;
    long off = (long)(byn * 16 + sn) * 16384 + m * 128 + ((ch ^ (m & 7)) << 4) + (n0 & 7) * 2;
    *(uint32_t*)(d_aslab + off) = hi;
    *(uint32_t*)(d_aslab + off + 8192) = lo;
  }
}

// ---------------- step kernel: bulk-fed pipeline + fused epilogue ----------------
// grid (32, 4): bx = n-tile (128 cols), by = k-chunk (1024). by 0-2 produce
// partials; by 3 reduces + RNN epilogue. 8 warps, warp tile 32x32 (2m x 4n).
__global__ void __launch_bounds__(256, 1) step_kernel(
    const float* __restrict__ v, const float* __restrict__ Wih, int t) {
  extern __shared__ __align__(1024) char smem[];
  const uint32_t sb = smem_u32(smem);
  const uint32_t mb = sb;
  const uint32_t buf = sb + 1024;
  const int tid = threadIdx.x;
  const int bx = blockIdx.x, by = blockIdx.y;
  const int nb = bx * 128;

  if (tid == 0) {
#pragma unroll
    for (int i = 0; i < 4; i++) MBAR_INIT(mb + 8 * i, 1);
  }
  __syncthreads();

  const unsigned long long wbase =
      (unsigned long long)__cvta_generic_to_global(d_wtile) +
      (unsigned long long)((by * 32 + bx) * 16) * 32768ull;
  const unsigned long long abase =
      (unsigned long long)__cvta_generic_to_global(d_aslab) +
      (unsigned long long)(((t & 1) * 4 + by) * 16) * 16384ull;

  auto issue = [&](int s) {
    const uint32_t st = buf + (uint32_t)(s & 3) * STG_BYTES;
    const uint32_t m = mb + (s & 3) * 8;
    MBAR_EXPECT_TX(m, STG_BYTES);
    BULK_G2S(st + OWH, wbase + (unsigned long long)s * 32768ull, 32768u, m);
    BULK_G2S(st + OAH, abase + (unsigned long long)s * 16384ull, 16384u, m);
  };
  if (tid == 0) { issue(0); issue(1); issue(2); }

  const int lane = tid & 31, warp = tid >> 5;
  const int wm = warp & 1, wn = warp >> 1;          // 2m x 4n warps
  const int mA0 = wm * 32 + (lane & 15);            // < 64
  const int nB0 = wn * 32 + (lane & 15);            // < 128
  const int halfk = lane >> 4;
  const uint32_t aA0 = (uint32_t)mA0 * 128, aA1 = aA0 + 16 * 128;
  const uint32_t aB0 = (uint32_t)nB0 * 128, aB1 = aB0 + 16 * 128;
  const uint32_t swA = (uint32_t)(mA0 & 7), swB = (uint32_t)(nB0 & 7);

  float acc[2][4][4];
#pragma unroll
  for (int mi = 0; mi < 2; mi++)
#pragma unroll
    for (int sl = 0; sl < 4; sl++)
#pragma unroll
      for (int f = 0; f < 4; f++) acc[mi][sl][f] = 0.0f;

  for (int s = 0; s < NSTG; s++) {
    mbar_wait(mb + (s & 3) * 8, (uint32_t)((s >> 2) & 1));
    const uint32_t st = buf + (uint32_t)(s & 3) * STG_BYTES;
#pragma unroll
    for (int k16 = 0; k16 < 4; k16++) {
      const uint32_t ch = (uint32_t)(k16 * 2 + halfk);
      const uint32_t xoA = (ch ^ swA) << 4;
      const uint32_t xoB = (ch ^ swB) << 4;
      uint32_t Ah[2][4], Al[2][4], Bh_[2][4], Bl_[2][4];
      LDSM4(Ah[0][0], Ah[0][1], Ah[0][2], Ah[0][3], st + OAH + aA0 + xoA);
      LDSM4(Ah[1][0], Ah[1][1], Ah[1][2], Ah[1][3], st + OAH + aA1 + xoA);
      LDSM4(Al[0][0], Al[0][1], Al[0][2], Al[0][3], st + OAL + aA0 + xoA);
      LDSM4(Al[1][0], Al[1][1], Al[1][2], Al[1][3], st + OAL + aA1 + xoA);
      LDSM4(Bh_[0][0], Bh_[0][1], Bh_[0][2], Bh_[0][3], st + OWH + aB0 + xoB);
      LDSM4(Bh_[1][0], Bh_[1][1], Bh_[1][2], Bh_[1][3], st + OWH + aB1 + xoB);
      LDSM4(Bl_[0][0], Bl_[0][1], Bl_[0][2], Bl_[0][3], st + OWL + aB0 + xoB);
      LDSM4(Bl_[1][0], Bl_[1][1], Bl_[1][2], Bl_[1][3], st + OWL + aB1 + xoB);
#pragma unroll
      for (int mi = 0; mi < 2; mi++)
#pragma unroll
        for (int bb = 0; bb < 2; bb++)
#pragma unroll
          for (int j = 0; j < 2; j++)
            MMA16816(acc[mi][bb * 2 + j], Ah[mi], Bh_[bb][j], Bh_[bb][j + 2]);
#pragma unroll
      for (int mi = 0; mi < 2; mi++)
#pragma unroll
        for (int bb = 0; bb < 2; bb++)
#pragma unroll
          for (int j = 0; j < 2; j++)
            MMA16816(acc[mi][bb * 2 + j], Ah[mi], Bl_[bb][j], Bl_[bb][j + 2]);
#pragma unroll
      for (int mi = 0; mi < 2; mi++)
#pragma unroll
        for (int bb = 0; bb < 2; bb++)
#pragma unroll
          for (int j = 0; j < 2; j++)
            MMA16816(acc[mi][bb * 2 + j], Al[mi], Bh_[bb][j], Bh_[bb][j + 2]);
    }
    __syncthreads();
    if (tid == 0 && s + 3 < NSTG) issue(s + 3);
  }

  const int r_ = lane >> 2, c_ = (lane & 3) * 2;

  if (by < 3) {
    float* pp = d_part + (long)by * (BB * NG);
#pragma unroll
    for (int mi = 0; mi < 2; mi++)
#pragma unroll
      for (int bb = 0; bb < 2; bb++)
#pragma unroll
        for (int j = 0; j < 2; j++)
#pragma unroll
          for (int rr = 0; rr < 2; rr++) {
            int m = wm * 32 + mi * 16 + r_ + rr * 8;
            int n = nb + wn * 32 + bb * 16 + j * 8 + c_;
            *(float2*)&pp[m * NG + n] =
                make_float2(acc[mi][bb * 2 + j][rr * 2], acc[mi][bb * 2 + j][rr * 2 + 1]);
          }
    __threadfence();
    __syncthreads();
    if (tid == 0) atomicAdd(&d_cnt[bx], 1);
  } else {
    if (tid == 0) {
      while (atomicCAS(&d_cnt[bx], 3, 0) != 3) __nanosleep(64);
    }
    __syncthreads();
    __threadfence();
    const float2* wih2 = (const float2*)Wih;
    const int p1 = (t + 1) & 1;
#pragma unroll
    for (int mi = 0; mi < 2; mi++)
#pragma unroll
      for (int rr = 0; rr < 2; rr++) {
        const int m = wm * 32 + mi * 16 + r_ + rr * 8;
        const float v0 = v[(m * TT + t) * 2 + 0];
        const float v1 = v[(m * TT + t) * 2 + 1];
        const int m_dec = m * TT + t;
        const int mt = m_dec >> 7, rdec = m_dec & 127;
#pragma unroll
        for (int bb = 0; bb < 2; bb++)
#pragma unroll
          for (int j = 0; j < 2; j++) {
            const int n0 = nb + wn * 32 + bb * 16 + j * 8 + c_;
            const int idx = m * NG + n0;
            float2 pa = *(const float2*)&d_part[idx];
            float2 pb = *(const float2*)&d_part[BB * NG + idx];
            float2 pc = *(const float2*)&d_part[2 * BB * NG + idx];
            float2 w0 = wih2[n0], w1 = wih2[n0 + 1];
            float z0 = acc[mi][bb * 2 + j][rr * 2] + pa.x + pb.x + pc.x + v0 * w0.x + v1 * w0.y;
            float z1 = acc[mi][bb * 2 + j][rr * 2 + 1] + pa.y + pb.y + pc.y + v0 * w1.x + v1 * w1.y;
            float2 va = *(const float2*)&d_va[idx];
            float2 zp = *(const float2*)&d_zp[idx];
            z0 -= 0.1f * va.x;
            z1 -= 0.1f * va.y;
            *(float2*)&d_va[idx] = make_float2(va.x + 0.9f * (zp.x - va.x),
                                               va.y + 0.9f * (zp.y - va.y));
            *(float2*)&d_zp[idx] = make_float2(z0, z1);
            float s0 = fmaxf(z0, 0.0f), s1 = fmaxf(z1, 0.0f);
            uint32_t hi, lo;
            split2(s0, s1, hi, lo);
            // g-slab (decode A): block (mt, kt) 32KB = hi 16KB | lo 16KB
            const int kt = n0 >> 6, chn = (n0 & 63) >> 3;
            long goff = (long)(mt * 64 + kt) * 32768 + rdec * 128 +
                        ((chn ^ (rdec & 7)) << 4) + (n0 & 7) * 2;
            *(uint32_t*)(d_gslab + goff) = hi;
            *(uint32_t*)(d_gslab + goff + 16384) = lo;
            // A-slab for next step
            const int byn = n0 >> 10, sn = (n0 & 1023) >> 6;
            long off = (long)((p1 * 4 + byn) * 16 + sn) * 16384 + m * 128 +
                       ((chn ^ (m & 7)) << 4) + (n0 & 7) * 2;
            *(uint32_t*)(d_aslab + off) = hi;
            *(uint32_t*)(d_aslab + off + 8192) = lo;
          }
      }
  }
}

// ---------------- decode: bulk-fed pipeline ----------------
// grid (8, 50): bx = 64-col n-tile of NP, by = 128-row m-tile of 6400.
// 8 warps: 4m x 2n, warp tile 32x32. K = 4096 = 64 stages of 64.
__global__ void __launch_bounds__(256, 1) decode_gemm(float* __restrict__ outp) {
  extern __shared__ __align__(1024) char smem[];
  const uint32_t sb = smem_u32(smem);
  const uint32_t mb = sb;
  const uint32_t buf = sb + 1024;
  const int tid = threadIdx.x;
  const int nx = blockIdx.x, mt = blockIdx.y;

  if (tid == 0) {
#pragma unroll
    for (int i = 0; i < 4; i++) MBAR_INIT(mb + 8 * i, 1);
  }
  __syncthreads();

  const unsigned long long gbase =
      (unsigned long long)__cvta_generic_to_global(d_gslab) +
      (unsigned long long)(mt * 64) * 32768ull;
  const unsigned long long wbase =
      (unsigned long long)__cvta_generic_to_global(d_wdtile) +
      (unsigned long long)(nx * 64) * 16384ull;

  auto issue = [&](int s) {
    const uint32_t st = buf + (uint32_t)(s & 3) * DSTG;
    const uint32_t m = mb + (s & 3) * 8;
    MBAR_EXPECT_TX(m, DSTG);
    BULK_G2S(st + D_OAH, gbase + (unsigned long long)s * 32768ull, 32768u, m);
    BULK_G2S(st + D_OWH, wbase + (unsigned long long)s * 16384ull, 16384u, m);
  };
  if (tid == 0) { issue(0); issue(1); issue(2); }

  const int lane = tid & 31, warp = tid >> 5;
  const int wm = warp & 3, wn = warp >> 2;          // 4m x 2n warps
  const int mA0 = wm * 32 + (lane & 15);            // < 128
  const int nB0 = wn * 32 + (lane & 15);            // < 64
  const int halfk = lane >> 4;
  const uint32_t aA0 = (uint32_t)mA0 * 128, aA1 = aA0 + 16 * 128;
  const uint32_t aB0 = (uint32_t)nB0 * 128, aB1 = aB0 + 16 * 128;
  const uint32_t swA = (uint32_t)(mA0 & 7), swB = (uint32_t)(nB0 & 7);

  float acc[2][4][4];
#pragma unroll
  for (int mi = 0; mi < 2; mi++)
#pragma unroll
    for (int sl = 0; sl < 4; sl++)
#pragma unroll
      for (int f = 0; f < 4; f++) acc[mi][sl][f] = 0.0f;

  for (int s = 0; s < 64; s++) {
    mbar_wait(mb + (s & 3) * 8, (uint32_t)((s >> 2) & 1));
    const uint32_t st = buf + (uint32_t)(s & 3) * DSTG;
#pragma unroll
    for (int k16 = 0; k16 < 4; k16++) {
      const uint32_t ch = (uint32_t)(k16 * 2 + halfk);
      const uint32_t xoA = (ch ^ swA) << 4;
      const uint32_t xoB = (ch ^ swB) << 4;
      uint32_t Ah[2][4], Al[2][4], Bh_[2][4], Bl_[2][4];
      LDSM4(Ah[0][0], Ah[0][1], Ah[0][2], Ah[0][3], st + D_OAH + aA0 + xoA);
      LDSM4(Ah[1][0], Ah[1][1], Ah[1][2], Ah[1][3], st + D_OAH + aA1 + xoA);
      LDSM4(Al[0][0], Al[0][1], Al[0][2], Al[0][3], st + D_OAL + aA0 + xoA);
      LDSM4(Al[1][0], Al[1][1], Al[1][2], Al[1][3], st + D_OAL + aA1 + xoA);
      LDSM4(Bh_[0][0], Bh_[0][1], Bh_[0][2], Bh_[0][3], st + D_OWH + aB0 + xoB);
      LDSM4(Bh_[1][0], Bh_[1][1], Bh_[1][2], Bh_[1][3], st + D_OWH + aB1 + xoB);
      LDSM4(Bl_[0][0], Bl_[0][1], Bl_[0][2], Bl_[0][3], st + D_OWL + aB0 + xoB);
      LDSM4(Bl_[1][0], Bl_[1][1], Bl_[1][2], Bl_[1][3], st + D_OWL + aB1 + xoB);
#pragma unroll
      for (int mi = 0; mi < 2; mi++)
#pragma unroll
        for (int bb = 0; bb < 2; bb++)
#pragma unroll
          for (int j = 0; j < 2; j++)
            MMA16816(acc[mi][bb * 2 + j], Ah[mi], Bh_[bb][j], Bh_[bb][j + 2]);
#pragma unroll
      for (int mi = 0; mi < 2; mi++)
#pragma unroll
        for (int bb = 0; bb < 2; bb++)
#pragma unroll
          for (int j = 0; j < 2; j++)
            MMA16816(acc[mi][bb * 2 + j], Ah[mi], Bl_[bb][j], Bl_[bb][j + 2]);
#pragma unroll
      for (int mi = 0; mi < 2; mi++)
#pragma unroll
        for (int bb = 0; bb < 2; bb++)
#pragma unroll
          for (int j = 0; j < 2; j++)
            MMA16816(acc[mi][bb * 2 + j], Al[mi], Bh_[bb][j], Bh_[bb][j + 2]);
    }
    __syncthreads();
    if (tid == 0 && s + 3 < 64) issue(s + 3);
  }

  const int r_ = lane >> 2, c_ = (lane & 3) * 2;
#pragma unroll
  for (int mi = 0; mi < 2; mi++)
#pragma unroll
    for (int bb = 0; bb < 2; bb++)
#pragma unroll
      for (int j = 0; j < 2; j++)
#pragma unroll
        for (int rr = 0; rr < 2; rr++) {
          long m = (long)mt * 128 + wm * 32 + mi * 16 + r_ + rr * 8;
          int n = nx * 64 + wn * 32 + bb * 16 + j * 8 + c_;
          *(float2*)&outp[m * NP + n] =
              make_float2(acc[mi][bb * 2 + j][rr * 2], acc[mi][bb * 2 + j][rr * 2 + 1]);
        }
}

// ---------------- launch ----------------
extern "C" void kernel_launch(void* const* d_in, const int* in_sizes, int n_in,
                              void* d_out, int out_size) {
  const float* v      = (const float*)d_in[0];
  const float* p0     = (const float*)d_in[1];
  const float* W_init = (const float*)d_in[2];
  const float* W_ih   = (const float*)d_in[3];
  const float* W_hh   = (const float*)d_in[4];
  const float* W_dec  = (const float*)d_in[5];
  float* out = (float*)d_out;

  cudaFuncSetAttribute(step_kernel, cudaFuncAttributeMaxDynamicSharedMemorySize, SMEM_STEP);
  cudaFuncSetAttribute(decode_gemm, cudaFuncAttributeMaxDynamicSharedMemorySize, SMEM_DEC);

  convert_whh<<<2048, 256>>>(W_hh);
  convert_wdec<<<256, 256>>>(W_dec);
  zero_state_kernel<<<128, 256>>>();
  h0_kernel<<<128, 256>>>(p0, W_init);

  for (int t = 0; t < TT; t++)
    step_kernel<<<dim3(32, 4), 256, SMEM_STEP>>>(v, W_ih, t);

  decode_gemm<<<dim3(8, 50), 256, SMEM_DEC>>>(out);
}